// round 8
// baseline (speedup 1.0000x reference)
#include <cuda_runtime.h>
#include <math.h>
#include <cstddef>
#include <cstdint>

// ---------------- problem constants ----------------
#define B_    4096
#define DIN   512
#define DH    1024
#define DOUT  256
#define DFF   4096
#define STEPS 30
#define LN_EPSF 1e-5f
#define GAMMA_F 0.17677669529663687f   // 0.5*sqrt(64/512)
#define NSM   148

// ---------------- device scratch (no allocations allowed) ----------------
__device__ float g_xemb[(size_t)B_ * DH];
__device__ float g_hA[(size_t)B_ * DH];
__device__ float g_hB[(size_t)B_ * DH];
__device__ int8_t g_W1q1[(size_t)DFF * DH];
__device__ int8_t g_W1q2[(size_t)DFF * DH];
__device__ int8_t g_W2q1[(size_t)DH * DFF];
__device__ int8_t g_W2q2[(size_t)DH * DFF];
__device__ float g_betaW1[DFF];
__device__ float g_betaW2[DH];
__device__ int8_t g_A1[(size_t)B_ * DH];
__device__ int8_t g_A2[(size_t)B_ * DH];
__device__ float g_alphaA[B_];
__device__ int8_t g_hid1[(size_t)B_ * DFF];
__device__ int8_t g_hid2[(size_t)B_ * DFF];
__device__ float g_u[4096];
__device__ float g_v[4096];
__device__ float g_t[4096];
__device__ float g_sig[2];

// ---------------- low-level helpers (plain sm_80+ features only) ----------------
__device__ __forceinline__ uint32_t smem_u32(const void* p) {
    uint32_t a;
    asm("{ .reg .u64 t; cvta.to.shared.u64 t, %1; cvt.u32.u64 %0, t; }" : "=r"(a) : "l"(p));
    return a;
}
__device__ __forceinline__ void cp_async16(uint32_t dst, const void* src) {
    asm volatile("cp.async.cg.shared.global [%0], [%1], 16;" :: "r"(dst), "l"(src) : "memory");
}
__device__ __forceinline__ void cp_commit() {
    asm volatile("cp.async.commit_group;" ::: "memory");
}
template<int N> __device__ __forceinline__ void cp_wait() {
    asm volatile("cp.async.wait_group %0;" :: "n"(N) : "memory");
}
__device__ __forceinline__ void ldm_x4(uint32_t addr, uint32_t* r) {
    asm volatile("ldmatrix.sync.aligned.m8n8.x4.shared.b16 {%0,%1,%2,%3}, [%4];"
        : "=r"(r[0]), "=r"(r[1]), "=r"(r[2]), "=r"(r[3]) : "r"(addr));
}
// m16n8k32 int8 MMA, s32 accumulate
__device__ __forceinline__ void mma_s8(int* d, const uint32_t* a, const uint32_t* b) {
    asm volatile("mma.sync.aligned.m16n8k32.row.col.s32.s8.s8.s32 "
        "{%0,%1,%2,%3}, {%4,%5,%6,%7}, {%8,%9}, {%0,%1,%2,%3};"
        : "+r"(d[0]), "+r"(d[1]), "+r"(d[2]), "+r"(d[3])
        : "r"(a[0]), "r"(a[1]), "r"(a[2]), "r"(a[3]), "r"(b[0]), "r"(b[1]));
}
// swizzled offset inside a tile: row r (64B rows), 16B-chunk c (0..3)
__device__ __forceinline__ uint32_t sw_off(int r, int c) {
    return ((uint32_t)r << 6) + (uint32_t)((c ^ ((r >> 1) & 3)) << 4);
}

// ---------------- small kernels: spectral norm ----------------
__global__ void init_vec_kernel(float* v, int n, float val) {
    int i = blockIdx.x * blockDim.x + threadIdx.x;
    if (i < n) v[i] = val;
}

__global__ void matvec_rows(const float* __restrict__ W, const float* __restrict__ v,
                            float* __restrict__ y, int C) {
    int row = blockIdx.x;
    const float* Wr = W + (size_t)row * C;
    float acc = 0.f;
    for (int j = threadIdx.x; j < C; j += 256) acc += Wr[j] * v[j];
    __shared__ float sm[8];
    #pragma unroll
    for (int o = 16; o > 0; o >>= 1) acc += __shfl_down_sync(0xffffffffu, acc, o);
    if ((threadIdx.x & 31) == 0) sm[threadIdx.x >> 5] = acc;
    __syncthreads();
    if (threadIdx.x < 8) {
        float a = sm[threadIdx.x];
        #pragma unroll
        for (int o = 4; o > 0; o >>= 1) a += __shfl_down_sync(0xffu, a, o);
        if (threadIdx.x == 0) y[row] = a;
    }
}

// z[col] += partial dot(W[:,col], u); grid (C/32, 8); z must be zeroed first
__global__ void matvec_cols(const float* __restrict__ W, const float* __restrict__ u,
                            float* __restrict__ z, int R, int C) {
    int lane = threadIdx.x & 31;
    int rp   = threadIdx.x >> 5;
    int col  = blockIdx.x * 32 + lane;
    int rchunk = R >> 3;
    int r0 = blockIdx.y * rchunk;
    int r1 = r0 + rchunk;
    float acc = 0.f;
    for (int i = r0 + rp; i < r1; i += 8) acc += W[(size_t)i * C + col] * u[i];
    __shared__ float sm[8][33];
    sm[rp][lane] = acc;
    __syncthreads();
    if (rp == 0) {
        float a = 0.f;
        #pragma unroll
        for (int r = 0; r < 8; r++) a += sm[r][lane];
        atomicAdd(&z[col], a);
    }
}

__global__ void normalize_vec(float* v, int n) {
    __shared__ float sm[32];
    __shared__ float s_inv;
    float acc = 0.f;
    for (int i = threadIdx.x; i < n; i += 1024) { float x = v[i]; acc += x * x; }
    #pragma unroll
    for (int o = 16; o > 0; o >>= 1) acc += __shfl_down_sync(0xffffffffu, acc, o);
    if ((threadIdx.x & 31) == 0) sm[threadIdx.x >> 5] = acc;
    __syncthreads();
    if (threadIdx.x < 32) {
        float a = sm[threadIdx.x];
        #pragma unroll
        for (int o = 16; o > 0; o >>= 1) a += __shfl_down_sync(0xffffffffu, a, o);
        if (threadIdx.x == 0) s_inv = 1.0f / (sqrtf(a) + 1e-12f);
    }
    __syncthreads();
    float inv = s_inv;
    for (int i = threadIdx.x; i < n; i += 1024) v[i] *= inv;
}

__global__ void dot_kernel(const float* __restrict__ a, const float* __restrict__ b,
                           float* __restrict__ out, int n) {
    __shared__ float sm[32];
    float acc = 0.f;
    for (int i = threadIdx.x; i < n; i += 1024) acc += a[i] * b[i];
    #pragma unroll
    for (int o = 16; o > 0; o >>= 1) acc += __shfl_down_sync(0xffffffffu, acc, o);
    if ((threadIdx.x & 31) == 0) sm[threadIdx.x >> 5] = acc;
    __syncthreads();
    if (threadIdx.x < 32) {
        float a2 = sm[threadIdx.x];
        #pragma unroll
        for (int o = 16; o > 0; o >>= 1) a2 += __shfl_down_sync(0xffffffffu, a2, o);
        if (threadIdx.x == 0) out[0] = a2;
    }
}

// quantize W/sigma per row: W/sig = beta*(q1 + q2/128), beta = rowmax/127
__global__ void quant_weights(const float* __restrict__ W, const float* __restrict__ sig,
                              int8_t* __restrict__ q1, int8_t* __restrict__ q2,
                              float* __restrict__ beta, int K) {
    int row = blockIdx.x;
    const float* Wr = W + (size_t)row * K;
    float inv = 1.0f / sig[0];
    float mx = 0.f;
    for (int j = threadIdx.x; j < K; j += 256) mx = fmaxf(mx, fabsf(Wr[j] * inv));
    __shared__ float sm[8];
    #pragma unroll
    for (int o = 16; o > 0; o >>= 1) mx = fmaxf(mx, __shfl_down_sync(0xffffffffu, mx, o));
    if ((threadIdx.x & 31) == 0) sm[threadIdx.x >> 5] = mx;
    __syncthreads();
    __shared__ float s_b;
    if (threadIdx.x < 8) {
        float a = sm[threadIdx.x];
        #pragma unroll
        for (int o = 4; o > 0; o >>= 1) a = fmaxf(a, __shfl_down_sync(0xffu, a, o));
        if (threadIdx.x == 0) s_b = fmaxf(a, 1e-20f) * (1.0f / 127.0f);
    }
    __syncthreads();
    float b = s_b, binv = 1.0f / b;
    if (threadIdx.x == 0) beta[row] = b;
    for (int j = threadIdx.x; j < K; j += 256) {
        float w = Wr[j] * inv;
        int v1 = __float2int_rn(w * binv);
        float resid = w - b * (float)v1;
        int v2 = __float2int_rn(resid * 128.0f * binv);
        size_t idx = (size_t)row * K + j;
        q1[idx] = (int8_t)v1;
        q2[idx] = (int8_t)v2;
    }
}

// ---------------- layernorm: fp32 in, two-level int8 out + per-row scale ----------------
__global__ void layernorm_quant(const float* __restrict__ h,
                                const float* __restrict__ g, const float* __restrict__ b,
                                int8_t* __restrict__ A1, int8_t* __restrict__ A2,
                                float* __restrict__ alpha) {
    int row = blockIdx.x;
    const float* hr = h + (size_t)row * DH;
    float s = 0.f, ss = 0.f;
    float xl[4];
    #pragma unroll
    for (int t = 0; t < 4; t++) {
        float x = hr[threadIdx.x + t * 256];
        xl[t] = x; s += x; ss += x * x;
    }
    __shared__ float sm1[8], sm2[8];
    #pragma unroll
    for (int o = 16; o > 0; o >>= 1) {
        s  += __shfl_down_sync(0xffffffffu, s, o);
        ss += __shfl_down_sync(0xffffffffu, ss, o);
    }
    if ((threadIdx.x & 31) == 0) { sm1[threadIdx.x >> 5] = s; sm2[threadIdx.x >> 5] = ss; }
    __syncthreads();
    __shared__ float s_mu, s_inv;
    if (threadIdx.x < 8) {
        float a = sm1[threadIdx.x], c = sm2[threadIdx.x];
        #pragma unroll
        for (int o = 4; o > 0; o >>= 1) {
            a += __shfl_down_sync(0xffu, a, o);
            c += __shfl_down_sync(0xffu, c, o);
        }
        if (threadIdx.x == 0) {
            float mu  = a * (1.0f / DH);
            float var = c * (1.0f / DH) - mu * mu;
            s_mu = mu; s_inv = rsqrtf(var + LN_EPSF);
        }
    }
    __syncthreads();
    float mu = s_mu, inv = s_inv;
    float y[4]; float mx = 0.f;
    #pragma unroll
    for (int t = 0; t < 4; t++) {
        int j = threadIdx.x + t * 256;
        y[t] = (xl[t] - mu) * inv * g[j] + b[j];
        mx = fmaxf(mx, fabsf(y[t]));
    }
    // row-max reduction
    #pragma unroll
    for (int o = 16; o > 0; o >>= 1) mx = fmaxf(mx, __shfl_down_sync(0xffffffffu, mx, o));
    if ((threadIdx.x & 31) == 0) sm1[threadIdx.x >> 5] = mx;
    __syncthreads();
    __shared__ float s_a;
    if (threadIdx.x < 8) {
        float a = sm1[threadIdx.x];
        #pragma unroll
        for (int o = 4; o > 0; o >>= 1) a = fmaxf(a, __shfl_down_sync(0xffu, a, o));
        if (threadIdx.x == 0) s_a = fmaxf(a, 1e-20f) * (1.0f / 127.0f);
    }
    __syncthreads();
    float al = s_a, ainv = 1.0f / al;
    if (threadIdx.x == 0) alpha[row] = al;
    #pragma unroll
    for (int t = 0; t < 4; t++) {
        int j = threadIdx.x + t * 256;
        int v1 = __float2int_rn(y[t] * ainv);
        float resid = y[t] - al * (float)v1;
        int v2 = __float2int_rn(resid * 128.0f * ainv);
        size_t idx = (size_t)row * DH + j;
        A1[idx] = (int8_t)v1;
        A2[idx] = (int8_t)v2;
    }
}

// ---------------- int8 two-level persistent GEMM ----------------
// C = alpha_m * beta_n * (A1*W1 + (A1*W2 + A2*W1)/128), epilogue fused.
// CTA tile 128x128, 8 warps (2x4), warp tile 64x32 = 4x4 m16n8k32 frags.
// Chunk = 64 K-elems (64B rows), 4-stage cp.async, XOR swizzle, persistent CTAs.
#define MSTAGES 4
#define TILE8   8192                      // 128 rows x 64 B
#define STAGEB  (4 * TILE8)               // A1, A2, W1, W2 = 32768 B
#define GSMEM   (MSTAGES * STAGEB)        // 131072 B

#define EPI_TANH 1
#define EPI_STEP 2

__device__ __forceinline__ void load_stage_s8(
    uint32_t sbase, int buf, int k0,
    const int8_t* __restrict__ A1, const int8_t* __restrict__ A2,
    const int8_t* __restrict__ W1, const int8_t* __restrict__ W2,
    int bm, int bn, int K, int tid)
{
    uint32_t base = sbase + (uint32_t)buf * STAGEB;
    #pragma unroll
    for (int j = 0; j < 8; j++) {
        int c = tid + j * 256;                  // 0..2047
        int t = c >> 9;                         // tile 0..3
        int rr = (c & 511) >> 2, c16 = c & 3;
        const int8_t* g = (t == 0) ? A1 : (t == 1) ? A2 : (t == 2) ? W1 : W2;
        int rowbase = (t < 2) ? bm : bn;
        cp_async16(base + (uint32_t)t * TILE8 + sw_off(rr, c16),
                   g + (size_t)(rowbase + rr) * K + k0 + c16 * 16);
    }
}

template <int EPI>
__global__ __launch_bounds__(256, 1) void gemm_s8(
    const int8_t* __restrict__ A1, const int8_t* __restrict__ A2,
    const int8_t* __restrict__ Wq1, const int8_t* __restrict__ Wq2,
    const float* __restrict__ betaW, const float* __restrict__ alphaA,
    const float* __restrict__ bias, int N, int K, int ntiles, int nx,
    float* __restrict__ Cf,
    int8_t* __restrict__ C1, int8_t* __restrict__ C2,
    const float* __restrict__ hprev, const float* __restrict__ xemb, float gamma) {

    extern __shared__ __align__(128) char smem[];
    uint32_t sb = smem_u32(smem);
    int tid = threadIdx.x, wid = tid >> 5, lane = tid & 31;
    int m0 = (wid >> 2) * 64, n0 = (wid & 3) * 32;   // warp tile 64x32
    int r16 = lane & 15, kh = lane >> 4;
    int g8 = lane >> 3, l8 = lane & 7;
    int qr = lane >> 2, qc = (lane & 3) * 2;
    const int nch = K >> 6;                          // 64 int8 per chunk

    for (int tile = blockIdx.x; tile < ntiles; tile += gridDim.x) {
        int bm = (tile / nx) * 128, bn = (tile % nx) * 128;

        int accP[4][4][4] = {};
        int accQ[4][4][4] = {};

        #pragma unroll
        for (int s = 0; s < MSTAGES - 1; s++) {
            load_stage_s8(sb, s, s << 6, A1, A2, Wq1, Wq2, bm, bn, K, tid);
            cp_commit();
        }

        for (int i = 0; i < nch; i++) {
            cp_wait<MSTAGES - 2>();
            __syncthreads();

            uint32_t st = sb + (uint32_t)(i & (MSTAGES - 1)) * STAGEB;
            #pragma unroll
            for (int ks = 0; ks < 2; ks++) {
                uint32_t a1f[4][4], a2f[4][4], w1f[2][4], w2f[2][4];
                #pragma unroll
                for (int mt = 0; mt < 4; mt++) {
                    uint32_t ar = st + sw_off(m0 + mt * 16 + r16, ks * 2 + kh);
                    ldm_x4(ar, a1f[mt]);
                    ldm_x4(ar + TILE8, a2f[mt]);
                }
                #pragma unroll
                for (int nh = 0; nh < 2; nh++) {
                    uint32_t br = st + 2 * TILE8 +
                        sw_off(n0 + nh * 16 + (g8 >> 1) * 8 + l8, ks * 2 + (g8 & 1));
                    ldm_x4(br, w1f[nh]);
                    ldm_x4(br + TILE8, w2f[nh]);
                }
                #pragma unroll
                for (int mt = 0; mt < 4; mt++)
                    #pragma unroll
                    for (int nt = 0; nt < 4; nt++)
                        mma_s8(accP[mt][nt], a1f[mt], &w1f[nt >> 1][(nt & 1) * 2]);
                #pragma unroll
                for (int mt = 0; mt < 4; mt++)
                    #pragma unroll
                    for (int nt = 0; nt < 4; nt++)
                        mma_s8(accQ[mt][nt], a1f[mt], &w2f[nt >> 1][(nt & 1) * 2]);
                #pragma unroll
                for (int mt = 0; mt < 4; mt++)
                    #pragma unroll
                    for (int nt = 0; nt < 4; nt++)
                        mma_s8(accQ[mt][nt], a2f[mt], &w1f[nt >> 1][(nt & 1) * 2]);
            }

            int nxt = i + MSTAGES - 1;
            if (nxt < nch)
                load_stage_s8(sb, nxt & (MSTAGES - 1), nxt << 6, A1, A2, Wq1, Wq2, bm, bn, K, tid);
            cp_commit();
        }

        // epilogue: dequant + bias + activation/step
        #pragma unroll
        for (int mt = 0; mt < 4; mt++) {
            #pragma unroll
            for (int nt = 0; nt < 4; nt++) {
                int c0 = bn + n0 + nt * 8 + qc;
                float bw0 = betaW[c0], bw1 = betaW[c0 + 1];
                float bz0 = bias[c0],  bz1 = bias[c0 + 1];
                #pragma unroll
                for (int h = 0; h < 2; h++) {
                    int r = bm + m0 + mt * 16 + qr + h * 8;
                    float aS = (EPI == EPI_TANH) ? alphaA[r] : (1.0f / 127.0f);
                    float P0 = (float)accP[mt][nt][h * 2 + 0];
                    float P1 = (float)accP[mt][nt][h * 2 + 1];
                    float Q0 = (float)accQ[mt][nt][h * 2 + 0];
                    float Q1 = (float)accQ[mt][nt][h * 2 + 1];
                    float v0 = aS * bw0 * (P0 + Q0 * 0.0078125f) + bz0;
                    float v1 = aS * bw1 * (P1 + Q1 * 0.0078125f) + bz1;
                    size_t idx = (size_t)r * N + c0;
                    if (EPI == EPI_TANH) {
                        float t0 = tanhf(v0), t1 = tanhf(v1);
                        int q10 = __float2int_rn(t0 * 127.0f);
                        int q11 = __float2int_rn(t1 * 127.0f);
                        float r0 = t0 - (float)q10 * (1.0f / 127.0f);
                        float r1 = t1 - (float)q11 * (1.0f / 127.0f);
                        int q20 = __float2int_rn(r0 * 16256.0f);   // 127*128
                        int q21 = __float2int_rn(r1 * 16256.0f);
                        char2 p1; p1.x = (char)q10; p1.y = (char)q11;
                        char2 p2; p2.x = (char)q20; p2.y = (char)q21;
                        *(char2*)(C1 + idx) = p1;
                        *(char2*)(C2 + idx) = p2;
                    } else {
                        float2 hp = *(const float2*)(hprev + idx);
                        float2 xe = *(const float2*)(xemb + idx);
                        float2 o;
                        o.x = (1.0f - gamma) * hp.x + gamma * (v0 + xe.x);
                        o.y = (1.0f - gamma) * hp.y + gamma * (v1 + xe.y);
                        *(float2*)(Cf + idx) = o;
                    }
                }
            }
        }
        __syncthreads();   // protect smem buffers before next tile's prologue
    }
}

// ---------------- fp32 SIMT GEMM (embed + head only) ----------------
#define BM 128
#define BN 128
#define BK 8
#define TM 8
#define TN 8

__global__ __launch_bounds__(256, 2) void gemm_f32_bias(
    const float* __restrict__ A, const float* __restrict__ W,
    const float* __restrict__ bias, float* __restrict__ C,
    int M, int N, int K) {

    __shared__ __align__(16) float As[BK][BM];
    __shared__ __align__(16) float Ws[BK][BN];

    int tid = threadIdx.x;
    int bm = blockIdx.y * BM, bn = blockIdx.x * BN;
    const float* Ablk = A + (size_t)bm * K;
    const float* Wblk = W + (size_t)bn * K;

    int lrow = tid >> 1;
    int lcol = (tid & 1) * 4;
    int ty = tid >> 4, tx = tid & 15;

    float acc[TM][TN] = {};

    for (int k0 = 0; k0 < K; k0 += BK) {
        float4 a4 = *reinterpret_cast<const float4*>(Ablk + (size_t)lrow * K + k0 + lcol);
        float4 w4 = *reinterpret_cast<const float4*>(Wblk + (size_t)lrow * K + k0 + lcol);
        As[lcol + 0][lrow] = a4.x; As[lcol + 1][lrow] = a4.y;
        As[lcol + 2][lrow] = a4.z; As[lcol + 3][lrow] = a4.w;
        Ws[lcol + 0][lrow] = w4.x; Ws[lcol + 1][lrow] = w4.y;
        Ws[lcol + 2][lrow] = w4.z; Ws[lcol + 3][lrow] = w4.w;
        __syncthreads();
        #pragma unroll
        for (int k = 0; k < BK; k++) {
            float4 a0 = *reinterpret_cast<const float4*>(&As[k][ty * TM]);
            float4 a1 = *reinterpret_cast<const float4*>(&As[k][ty * TM + 4]);
            float4 w0 = *reinterpret_cast<const float4*>(&Ws[k][tx * TN]);
            float4 w1 = *reinterpret_cast<const float4*>(&Ws[k][tx * TN + 4]);
            float ra[TM] = {a0.x, a0.y, a0.z, a0.w, a1.x, a1.y, a1.z, a1.w};
            float rw[TN] = {w0.x, w0.y, w0.z, w0.w, w1.x, w1.y, w1.z, w1.w};
            #pragma unroll
            for (int i = 0; i < TM; i++)
                #pragma unroll
                for (int j = 0; j < TN; j++)
                    acc[i][j] += ra[i] * rw[j];
        }
        __syncthreads();
    }

    #pragma unroll
    for (int i = 0; i < TM; i++) {
        int m = bm + ty * TM + i;
        #pragma unroll
        for (int j = 0; j < TN; j++) {
            int n = bn + tx * TN + j;
            C[(size_t)m * N + n] = acc[i][j] + bias[n];
        }
    }
}

// ---------------- host-side helpers ----------------
static void spectral_sigma(const float* W, int R, int C,
                           float* u, float* v, float* t, float* sig) {
    float v0 = 1.0f / sqrtf((float)C);
    init_vec_kernel<<<(C + 255) / 256, 256>>>(v, C, v0);
    for (int it = 0; it < 15; it++) {
        matvec_rows<<<R, 256>>>(W, v, u, C);
        normalize_vec<<<1, 1024>>>(u, R);
        init_vec_kernel<<<(C + 255) / 256, 256>>>(v, C, 0.f);
        matvec_cols<<<dim3(C / 32, 8), 256>>>(W, u, v, R, C);
        normalize_vec<<<1, 1024>>>(v, C);
    }
    matvec_rows<<<R, 256>>>(W, v, t, C);
    dot_kernel<<<1, 1024>>>(u, t, sig, R);
}

extern "C" void kernel_launch(void* const* d_in, const int* in_sizes, int n_in,
                              void* d_out, int out_size) {
    const float* x       = (const float*)d_in[0];
    const float* embed_w = (const float*)d_in[1];
    const float* embed_b = (const float*)d_in[2];
    const float* W1      = (const float*)d_in[3];
    const float* b1      = (const float*)d_in[4];
    const float* W2      = (const float*)d_in[5];
    const float* b2      = (const float*)d_in[6];
    const float* ln_g    = (const float*)d_in[7];
    const float* ln_b    = (const float*)d_in[8];
    const float* head_w  = (const float*)d_in[9];
    const float* head_b  = (const float*)d_in[10];
    float* out = (float*)d_out;

    float *p_xemb, *p_hA, *p_hB, *p_u, *p_v, *p_t, *p_sig;
    float *p_betaW1, *p_betaW2, *p_alphaA;
    int8_t *p_W1q1, *p_W1q2, *p_W2q1, *p_W2q2, *p_A1, *p_A2, *p_hid1, *p_hid2;
    cudaGetSymbolAddress((void**)&p_xemb, g_xemb);
    cudaGetSymbolAddress((void**)&p_hA, g_hA);
    cudaGetSymbolAddress((void**)&p_hB, g_hB);
    cudaGetSymbolAddress((void**)&p_u, g_u);
    cudaGetSymbolAddress((void**)&p_v, g_v);
    cudaGetSymbolAddress((void**)&p_t, g_t);
    cudaGetSymbolAddress((void**)&p_sig, g_sig);
    cudaGetSymbolAddress((void**)&p_W1q1, g_W1q1);
    cudaGetSymbolAddress((void**)&p_W1q2, g_W1q2);
    cudaGetSymbolAddress((void**)&p_W2q1, g_W2q1);
    cudaGetSymbolAddress((void**)&p_W2q2, g_W2q2);
    cudaGetSymbolAddress((void**)&p_betaW1, g_betaW1);
    cudaGetSymbolAddress((void**)&p_betaW2, g_betaW2);
    cudaGetSymbolAddress((void**)&p_A1, g_A1);
    cudaGetSymbolAddress((void**)&p_A2, g_A2);
    cudaGetSymbolAddress((void**)&p_alphaA, g_alphaA);
    cudaGetSymbolAddress((void**)&p_hid1, g_hid1);
    cudaGetSymbolAddress((void**)&p_hid2, g_hid2);

    cudaFuncSetAttribute(gemm_s8<EPI_TANH>,
                         cudaFuncAttributeMaxDynamicSharedMemorySize, GSMEM);
    cudaFuncSetAttribute(gemm_s8<EPI_STEP>,
                         cudaFuncAttributeMaxDynamicSharedMemorySize, GSMEM);

    // spectral sigma + two-level int8 quantization of W1n, W2n
    spectral_sigma(W1, DFF, DH, p_u, p_v, p_t, p_sig);
    quant_weights<<<DFF, 256>>>(W1, p_sig, p_W1q1, p_W1q2, p_betaW1, DH);
    spectral_sigma(W2, DH, DFF, p_u, p_v, p_t, p_sig);
    quant_weights<<<DH, 256>>>(W2, p_sig, p_W2q1, p_W2q2, p_betaW2, DFF);

    // x_emb = x @ embed_w^T + embed_b  (fp32 SIMT)
    gemm_f32_bias<<<dim3(DH / BN, B_ / BM), 256>>>(x, embed_w, embed_b, p_xemb, B_, DH, DIN);

    // h0 = x_emb
    cudaMemcpyAsync(p_hA, p_xemb, (size_t)B_ * DH * sizeof(float), cudaMemcpyDeviceToDevice);

    const int nt1 = (B_ / 128) * (DFF / 128);   // 1024 tiles, nx=32
    const int nt2 = (B_ / 128) * (DH / 128);    // 256 tiles,  nx=8

    float* hc = p_hA;
    float* hx = p_hB;
    for (int s = 0; s < STEPS; s++) {
        layernorm_quant<<<B_, 256>>>(hc, ln_g, ln_b, p_A1, p_A2, p_alphaA);
        gemm_s8<EPI_TANH><<<NSM, 256, GSMEM>>>(
            p_A1, p_A2, p_W1q1, p_W1q2, p_betaW1, p_alphaA, b1, DFF, DH, nt1, DFF / 128,
            nullptr, p_hid1, p_hid2, nullptr, nullptr, 0.f);
        gemm_s8<EPI_STEP><<<NSM, 256, GSMEM>>>(
            p_hid1, p_hid2, p_W2q1, p_W2q2, p_betaW2, nullptr, b2, DH, DFF, nt2, DH / 128,
            hx, nullptr, nullptr, hc, p_xemb, GAMMA_F);
        float* tmp = hc; hc = hx; hx = tmp;
    }

    // out = h @ head_w^T + head_b (fp32 SIMT)
    gemm_f32_bias<<<dim3(DOUT / BN, B_ / BM), 256>>>(hc, head_w, head_b, out, B_, DOUT, DH);
}

// round 9
// speedup vs baseline: 3.7059x; 3.7059x over previous
#include <cuda_runtime.h>
#include <cuda_fp16.h>
#include <math.h>
#include <cstddef>
#include <cstdint>

// ---------------- problem constants ----------------
#define B_    4096
#define DIN   512
#define DH    1024
#define DOUT  256
#define DFF   4096
#define STEPS 30
#define LN_EPSF 1e-5f
#define GAMMA_F 0.17677669529663687f   // 0.5*sqrt(64/512)
#define NSM   148

// ---------------- device scratch (no allocations allowed) ----------------
__device__ float g_xemb[(size_t)B_ * DH];
__device__ float g_hA[(size_t)B_ * DH];
__device__ float g_hB[(size_t)B_ * DH];
__device__ __half g_W1h[(size_t)DFF * DH];
__device__ __half g_W2h[(size_t)DH * DFF];
__device__ __half g_hnhi[(size_t)B_ * DH];
__device__ __half g_hnlo[(size_t)B_ * DH];
__device__ __half g_hidhi[(size_t)B_ * DFF];
__device__ __half g_hidlo[(size_t)B_ * DFF];
__device__ float g_u[4096];
__device__ float g_v[4096];
__device__ float g_t[4096];
__device__ float g_sig[2];

// ---------------- low-level helpers (plain sm_80+ features only) ----------------
__device__ __forceinline__ uint32_t smem_u32(const void* p) {
    uint32_t a;
    asm("{ .reg .u64 t; cvta.to.shared.u64 t, %1; cvt.u32.u64 %0, t; }" : "=r"(a) : "l"(p));
    return a;
}
__device__ __forceinline__ void cp_async16(uint32_t dst, const void* src) {
    asm volatile("cp.async.cg.shared.global [%0], [%1], 16;" :: "r"(dst), "l"(src) : "memory");
}
__device__ __forceinline__ void cp_commit() {
    asm volatile("cp.async.commit_group;" ::: "memory");
}
template<int N> __device__ __forceinline__ void cp_wait() {
    asm volatile("cp.async.wait_group %0;" :: "n"(N) : "memory");
}
__device__ __forceinline__ void ldm_x4(uint32_t addr, uint32_t* r) {
    asm volatile("ldmatrix.sync.aligned.m8n8.x4.shared.b16 {%0,%1,%2,%3}, [%4];"
        : "=r"(r[0]), "=r"(r[1]), "=r"(r[2]), "=r"(r[3]) : "r"(addr));
}
// fp16 m16n8k16 MMA, fp32 accumulate
__device__ __forceinline__ void mma_f16(float* d, const uint32_t* a, const uint32_t* b) {
    asm volatile("mma.sync.aligned.m16n8k16.row.col.f32.f16.f16.f32 "
        "{%0,%1,%2,%3}, {%4,%5,%6,%7}, {%8,%9}, {%0,%1,%2,%3};"
        : "+f"(d[0]), "+f"(d[1]), "+f"(d[2]), "+f"(d[3])
        : "r"(a[0]), "r"(a[1]), "r"(a[2]), "r"(a[3]), "r"(b[0]), "r"(b[1]));
}
// swizzled offset inside a tile: row r (64B rows), 16B-chunk c (0..3)
__device__ __forceinline__ uint32_t sw_off(int r, int c) {
    return ((uint32_t)r << 6) + (uint32_t)((c ^ ((r >> 1) & 3)) << 4);
}

// ---------------- small kernels: spectral norm ----------------
__global__ void init_vec_kernel(float* v, int n, float val) {
    int i = blockIdx.x * blockDim.x + threadIdx.x;
    if (i < n) v[i] = val;
}

__global__ void matvec_rows(const float* __restrict__ W, const float* __restrict__ v,
                            float* __restrict__ y, int C) {
    int row = blockIdx.x;
    const float* Wr = W + (size_t)row * C;
    float acc = 0.f;
    for (int j = threadIdx.x; j < C; j += 256) acc += Wr[j] * v[j];
    __shared__ float sm[8];
    #pragma unroll
    for (int o = 16; o > 0; o >>= 1) acc += __shfl_down_sync(0xffffffffu, acc, o);
    if ((threadIdx.x & 31) == 0) sm[threadIdx.x >> 5] = acc;
    __syncthreads();
    if (threadIdx.x < 8) {
        float a = sm[threadIdx.x];
        #pragma unroll
        for (int o = 4; o > 0; o >>= 1) a += __shfl_down_sync(0xffu, a, o);
        if (threadIdx.x == 0) y[row] = a;
    }
}

// z[col] += partial dot(W[:,col], u); grid (C/32, 8); z must be zeroed first
__global__ void matvec_cols(const float* __restrict__ W, const float* __restrict__ u,
                            float* __restrict__ z, int R, int C) {
    int lane = threadIdx.x & 31;
    int rp   = threadIdx.x >> 5;
    int col  = blockIdx.x * 32 + lane;
    int rchunk = R >> 3;
    int r0 = blockIdx.y * rchunk;
    int r1 = r0 + rchunk;
    float acc = 0.f;
    for (int i = r0 + rp; i < r1; i += 8) acc += W[(size_t)i * C + col] * u[i];
    __shared__ float sm[8][33];
    sm[rp][lane] = acc;
    __syncthreads();
    if (rp == 0) {
        float a = 0.f;
        #pragma unroll
        for (int r = 0; r < 8; r++) a += sm[r][lane];
        atomicAdd(&z[col], a);
    }
}

__global__ void normalize_vec(float* v, int n) {
    __shared__ float sm[32];
    __shared__ float s_inv;
    float acc = 0.f;
    for (int i = threadIdx.x; i < n; i += 1024) { float x = v[i]; acc += x * x; }
    #pragma unroll
    for (int o = 16; o > 0; o >>= 1) acc += __shfl_down_sync(0xffffffffu, acc, o);
    if ((threadIdx.x & 31) == 0) sm[threadIdx.x >> 5] = acc;
    __syncthreads();
    if (threadIdx.x < 32) {
        float a = sm[threadIdx.x];
        #pragma unroll
        for (int o = 16; o > 0; o >>= 1) a = a + __shfl_down_sync(0xffffffffu, a, o);
        if (threadIdx.x == 0) s_inv = 1.0f / (sqrtf(a) + 1e-12f);
    }
    __syncthreads();
    float inv = s_inv;
    for (int i = threadIdx.x; i < n; i += 1024) v[i] *= inv;
}

__global__ void dot_kernel(const float* __restrict__ a, const float* __restrict__ b,
                           float* __restrict__ out, int n) {
    __shared__ float sm[32];
    float acc = 0.f;
    for (int i = threadIdx.x; i < n; i += 1024) acc += a[i] * b[i];
    #pragma unroll
    for (int o = 16; o > 0; o >>= 1) acc += __shfl_down_sync(0xffffffffu, acc, o);
    if ((threadIdx.x & 31) == 0) sm[threadIdx.x >> 5] = acc;
    __syncthreads();
    if (threadIdx.x < 32) {
        float a2 = sm[threadIdx.x];
        #pragma unroll
        for (int o = 16; o > 0; o >>= 1) a2 += __shfl_down_sync(0xffffffffu, a2, o);
        if (threadIdx.x == 0) out[0] = a2;
    }
}

// Wh = fp16(W / sigma)
__global__ void scale_half(const float* __restrict__ W, const float* __restrict__ sig,
                           __half* __restrict__ Wh, size_t n) {
    float inv = 1.0f / sig[0];
    size_t stride = (size_t)gridDim.x * blockDim.x;
    for (size_t i = (size_t)blockIdx.x * blockDim.x + threadIdx.x; i < n; i += stride)
        Wh[i] = __float2half_rn(W[i] * inv);
}

// ---------------- layernorm: fp32 in, fp16 hi/lo out ----------------
__global__ void layernorm_split(const float* __restrict__ h,
                                const float* __restrict__ g, const float* __restrict__ b,
                                __half* __restrict__ ohi, __half* __restrict__ olo) {
    int row = blockIdx.x;
    const float* hr = h + (size_t)row * DH;
    float s = 0.f, ss = 0.f;
    float xl[4];
    #pragma unroll
    for (int t = 0; t < 4; t++) {
        float x = hr[threadIdx.x + t * 256];
        xl[t] = x; s += x; ss += x * x;
    }
    __shared__ float sm1[8], sm2[8];
    #pragma unroll
    for (int o = 16; o > 0; o >>= 1) {
        s  += __shfl_down_sync(0xffffffffu, s, o);
        ss += __shfl_down_sync(0xffffffffu, ss, o);
    }
    if ((threadIdx.x & 31) == 0) { sm1[threadIdx.x >> 5] = s; sm2[threadIdx.x >> 5] = ss; }
    __syncthreads();
    __shared__ float s_mu, s_inv;
    if (threadIdx.x < 8) {
        float a = sm1[threadIdx.x], c = sm2[threadIdx.x];
        #pragma unroll
        for (int o = 4; o > 0; o >>= 1) {
            a += __shfl_down_sync(0xffu, a, o);
            c += __shfl_down_sync(0xffu, c, o);
        }
        if (threadIdx.x == 0) {
            float mu  = a * (1.0f / DH);
            float var = c * (1.0f / DH) - mu * mu;
            s_mu = mu; s_inv = rsqrtf(var + LN_EPSF);
        }
    }
    __syncthreads();
    float mu = s_mu, inv = s_inv;
    #pragma unroll
    for (int t = 0; t < 4; t++) {
        int j = threadIdx.x + t * 256;
        float y = (xl[t] - mu) * inv * g[j] + b[j];
        __half hh = __float2half_rn(y);
        size_t idx = (size_t)row * DH + j;
        ohi[idx] = hh;
        olo[idx] = __float2half_rn(y - __half2float(hh));
    }
}

// ---------------- fp16 2-term persistent GEMM ----------------
// C[M,N] = (Ahi+Alo)[M,K] @ (Wh[N,K])^T  -- A to 2^-24, W to fp16.
// CTA tile 256x128, 8 warps (4x2), warp tile 64x64 = 4x8 m16n8k16 frags.
// BK=32, 4-stage cp.async, 64B XOR-swizzled rows, persistent CTAs.
#define MSTAGES 4
#define ATILEB  (256 * 64)               // 16384 B: 256x32 fp16 tile
#define WTILEB  (128 * 64)               //  8192 B: 128x32 fp16 tile
#define STAGEB  (2 * ATILEB + WTILEB)    // 40960 B (Ahi, Alo, Wh)
#define GSMEM   (MSTAGES * STAGEB)       // 163840 B

#define EPI_TANH 1
#define EPI_STEP 2

__device__ __forceinline__ void load_stage(
    uint32_t sbase, int buf, int k0,
    const __half* __restrict__ Ahi, const __half* __restrict__ Alo,
    const __half* __restrict__ Wh,
    int bm, int bn, int K, int tid)
{
    uint32_t base = sbase + (uint32_t)buf * STAGEB;
    // A: 2 parts x 256 rows x 4 16B-chunks = 2048 lane-ops (8/thread)
    #pragma unroll
    for (int j = 0; j < 8; j++) {
        int c = tid + j * 256;                  // 0..2047
        int part = c >> 10;                     // 0=hi, 1=lo
        int rr = (c & 1023) >> 2, c16 = c & 3;
        const __half* g = part ? Alo : Ahi;
        cp_async16(base + (uint32_t)part * ATILEB + sw_off(rr, c16),
                   g + (size_t)(bm + rr) * K + k0 + c16 * 8);
    }
    // W: 128 rows x 4 chunks = 512 lane-ops (2/thread)
    #pragma unroll
    for (int j = 0; j < 2; j++) {
        int c = tid + j * 256;                  // 0..511
        int rr = c >> 2, c16 = c & 3;
        cp_async16(base + 2u * ATILEB + sw_off(rr, c16),
                   Wh + (size_t)(bn + rr) * K + k0 + c16 * 8);
    }
}

template <int EPI>
__global__ __launch_bounds__(256, 1) void gemm_f16x2(
    const __half* __restrict__ Ahi, const __half* __restrict__ Alo,
    const __half* __restrict__ Wh,
    const float* __restrict__ bias, int N, int K, int ntiles, int nx,
    float* __restrict__ Cf,
    __half* __restrict__ Chi, __half* __restrict__ Clo,
    const float* __restrict__ hprev, const float* __restrict__ xemb, float gamma) {

    extern __shared__ __align__(128) char smem[];
    uint32_t sb = smem_u32(smem);
    int tid = threadIdx.x, wid = tid >> 5, lane = tid & 31;
    int m0 = (wid >> 1) * 64, n0 = (wid & 1) * 64;   // warp tile 64x64
    int r16 = lane & 15, kh = lane >> 4;
    int g8 = lane >> 3, l8 = lane & 7;
    int qr = lane >> 2, qc = (lane & 3) * 2;
    const int nch = K >> 5;

    for (int tile = blockIdx.x; tile < ntiles; tile += gridDim.x) {
        int bm = (tile / nx) * 256, bn = (tile % nx) * 128;

        float acc[4][8][4] = {};

        #pragma unroll
        for (int s = 0; s < MSTAGES - 1; s++) {
            load_stage(sb, s, s << 5, Ahi, Alo, Wh, bm, bn, K, tid);
            cp_commit();
        }

        for (int i = 0; i < nch; i++) {
            cp_wait<MSTAGES - 2>();
            __syncthreads();

            uint32_t st = sb + (uint32_t)(i & (MSTAGES - 1)) * STAGEB;
            #pragma unroll
            for (int ks = 0; ks < 2; ks++) {
                uint32_t a_hi[4][4], a_lo[4][4], w[4][4];
                #pragma unroll
                for (int mt = 0; mt < 4; mt++) {
                    uint32_t ar = st + sw_off(m0 + mt * 16 + r16, ks * 2 + kh);
                    ldm_x4(ar, a_hi[mt]);
                    ldm_x4(ar + ATILEB, a_lo[mt]);
                }
                #pragma unroll
                for (int nh = 0; nh < 4; nh++) {
                    uint32_t br = st + 2 * ATILEB +
                        sw_off(n0 + nh * 16 + (g8 >> 1) * 8 + l8, ks * 2 + (g8 & 1));
                    ldm_x4(br, w[nh]);
                }
                // term-outer: 32 independent MMAs per term
                #pragma unroll
                for (int mt = 0; mt < 4; mt++)
                    #pragma unroll
                    for (int nt = 0; nt < 8; nt++)
                        mma_f16(acc[mt][nt], a_hi[mt], &w[nt >> 1][(nt & 1) * 2]);
                #pragma unroll
                for (int mt = 0; mt < 4; mt++)
                    #pragma unroll
                    for (int nt = 0; nt < 8; nt++)
                        mma_f16(acc[mt][nt], a_lo[mt], &w[nt >> 1][(nt & 1) * 2]);
            }

            int nxt = i + MSTAGES - 1;
            if (nxt < nch)
                load_stage(sb, nxt & (MSTAGES - 1), nxt << 5, Ahi, Alo, Wh, bm, bn, K, tid);
            cp_commit();
        }

        // epilogue from accumulator registers
        #pragma unroll
        for (int mt = 0; mt < 4; mt++) {
            #pragma unroll
            for (int nt = 0; nt < 8; nt++) {
                int c0 = bn + n0 + nt * 8 + qc;
                float2 bz = *(const float2*)(bias + c0);
                #pragma unroll
                for (int h = 0; h < 2; h++) {
                    int r = bm + m0 + mt * 16 + qr + h * 8;
                    float v0 = acc[mt][nt][h * 2 + 0] + bz.x;
                    float v1 = acc[mt][nt][h * 2 + 1] + bz.y;
                    size_t idx = (size_t)r * N + c0;
                    if (EPI == EPI_TANH) {
                        float t0 = tanhf(v0), t1 = tanhf(v1);
                        __half h0 = __float2half_rn(t0), h1 = __float2half_rn(t1);
                        __half2 hp; hp.x = h0; hp.y = h1;
                        __half2 lp;
                        lp.x = __float2half_rn(t0 - __half2float(h0));
                        lp.y = __float2half_rn(t1 - __half2float(h1));
                        *(__half2*)(Chi + idx) = hp;
                        *(__half2*)(Clo + idx) = lp;
                    } else {
                        float2 hp = *(const float2*)(hprev + idx);
                        float2 xe = *(const float2*)(xemb + idx);
                        float2 o;
                        o.x = (1.0f - gamma) * hp.x + gamma * (v0 + xe.x);
                        o.y = (1.0f - gamma) * hp.y + gamma * (v1 + xe.y);
                        *(float2*)(Cf + idx) = o;
                    }
                }
            }
        }
        __syncthreads();   // protect smem buffers before next tile's prologue
    }
}

// ---------------- fp32 SIMT GEMM (embed + head only) ----------------
#define BM 128
#define BN 128
#define BK 8
#define TM 8
#define TN 8

__global__ __launch_bounds__(256, 2) void gemm_f32_bias(
    const float* __restrict__ A, const float* __restrict__ W,
    const float* __restrict__ bias, float* __restrict__ C,
    int M, int N, int K) {

    __shared__ __align__(16) float As[BK][BM];
    __shared__ __align__(16) float Ws[BK][BN];

    int tid = threadIdx.x;
    int bm = blockIdx.y * BM, bn = blockIdx.x * BN;
    const float* Ablk = A + (size_t)bm * K;
    const float* Wblk = W + (size_t)bn * K;

    int lrow = tid >> 1;
    int lcol = (tid & 1) * 4;
    int ty = tid >> 4, tx = tid & 15;

    float acc[TM][TN] = {};

    for (int k0 = 0; k0 < K; k0 += BK) {
        float4 a4 = *reinterpret_cast<const float4*>(Ablk + (size_t)lrow * K + k0 + lcol);
        float4 w4 = *reinterpret_cast<const float4*>(Wblk + (size_t)lrow * K + k0 + lcol);
        As[lcol + 0][lrow] = a4.x; As[lcol + 1][lrow] = a4.y;
        As[lcol + 2][lrow] = a4.z; As[lcol + 3][lrow] = a4.w;
        Ws[lcol + 0][lrow] = w4.x; Ws[lcol + 1][lrow] = w4.y;
        Ws[lcol + 2][lrow] = w4.z; Ws[lcol + 3][lrow] = w4.w;
        __syncthreads();
        #pragma unroll
        for (int k = 0; k < BK; k++) {
            float4 a0 = *reinterpret_cast<const float4*>(&As[k][ty * TM]);
            float4 a1 = *reinterpret_cast<const float4*>(&As[k][ty * TM + 4]);
            float4 w0 = *reinterpret_cast<const float4*>(&Ws[k][tx * TN]);
            float4 w1 = *reinterpret_cast<const float4*>(&Ws[k][tx * TN + 4]);
            float ra[TM] = {a0.x, a0.y, a0.z, a0.w, a1.x, a1.y, a1.z, a1.w};
            float rw[TN] = {w0.x, w0.y, w0.z, w0.w, w1.x, w1.y, w1.z, w1.w};
            #pragma unroll
            for (int i = 0; i < TM; i++)
                #pragma unroll
                for (int j = 0; j < TN; j++)
                    acc[i][j] += ra[i] * rw[j];
        }
        __syncthreads();
    }

    #pragma unroll
    for (int i = 0; i < TM; i++) {
        int m = bm + ty * TM + i;
        #pragma unroll
        for (int j = 0; j < TN; j++) {
            int n = bn + tx * TN + j;
            C[(size_t)m * N + n] = acc[i][j] + bias[n];
        }
    }
}

// ---------------- host-side helpers ----------------
static void spectral_sigma(const float* W, int R, int C,
                           float* u, float* v, float* t, float* sig) {
    float v0 = 1.0f / sqrtf((float)C);
    init_vec_kernel<<<(C + 255) / 256, 256>>>(v, C, v0);
    for (int it = 0; it < 15; it++) {
        matvec_rows<<<R, 256>>>(W, v, u, C);
        normalize_vec<<<1, 1024>>>(u, R);
        init_vec_kernel<<<(C + 255) / 256, 256>>>(v, C, 0.f);
        matvec_cols<<<dim3(C / 32, 8), 256>>>(W, u, v, R, C);
        normalize_vec<<<1, 1024>>>(v, C);
    }
    matvec_rows<<<R, 256>>>(W, v, t, C);
    dot_kernel<<<1, 1024>>>(u, t, sig, R);
}

extern "C" void kernel_launch(void* const* d_in, const int* in_sizes, int n_in,
                              void* d_out, int out_size) {
    const float* x       = (const float*)d_in[0];
    const float* embed_w = (const float*)d_in[1];
    const float* embed_b = (const float*)d_in[2];
    const float* W1      = (const float*)d_in[3];
    const float* b1      = (const float*)d_in[4];
    const float* W2      = (const float*)d_in[5];
    const float* b2      = (const float*)d_in[6];
    const float* ln_g    = (const float*)d_in[7];
    const float* ln_b    = (const float*)d_in[8];
    const float* head_w  = (const float*)d_in[9];
    const float* head_b  = (const float*)d_in[10];
    float* out = (float*)d_out;

    float *p_xemb, *p_hA, *p_hB, *p_u, *p_v, *p_t, *p_sig;
    __half *p_W1h, *p_W2h, *p_hnhi, *p_hnlo, *p_hidhi, *p_hidlo;
    cudaGetSymbolAddress((void**)&p_xemb, g_xemb);
    cudaGetSymbolAddress((void**)&p_hA, g_hA);
    cudaGetSymbolAddress((void**)&p_hB, g_hB);
    cudaGetSymbolAddress((void**)&p_u, g_u);
    cudaGetSymbolAddress((void**)&p_v, g_v);
    cudaGetSymbolAddress((void**)&p_t, g_t);
    cudaGetSymbolAddress((void**)&p_sig, g_sig);
    cudaGetSymbolAddress((void**)&p_W1h, g_W1h);
    cudaGetSymbolAddress((void**)&p_W2h, g_W2h);
    cudaGetSymbolAddress((void**)&p_hnhi, g_hnhi);
    cudaGetSymbolAddress((void**)&p_hnlo, g_hnlo);
    cudaGetSymbolAddress((void**)&p_hidhi, g_hidhi);
    cudaGetSymbolAddress((void**)&p_hidlo, g_hidlo);

    cudaFuncSetAttribute(gemm_f16x2<EPI_TANH>,
                         cudaFuncAttributeMaxDynamicSharedMemorySize, GSMEM);
    cudaFuncSetAttribute(gemm_f16x2<EPI_STEP>,
                         cudaFuncAttributeMaxDynamicSharedMemorySize, GSMEM);

    // spectral sigma + fp16 weights
    spectral_sigma(W1, DFF, DH, p_u, p_v, p_t, p_sig);
    scale_half<<<2048, 256>>>(W1, p_sig, p_W1h, (size_t)DFF * DH);
    spectral_sigma(W2, DH, DFF, p_u, p_v, p_t, p_sig);
    scale_half<<<2048, 256>>>(W2, p_sig, p_W2h, (size_t)DH * DFF);

    // x_emb = x @ embed_w^T + embed_b  (fp32 SIMT)
    gemm_f32_bias<<<dim3(DH / BN, B_ / BM), 256>>>(x, embed_w, embed_b, p_xemb, B_, DH, DIN);

    // h0 = x_emb
    cudaMemcpyAsync(p_hA, p_xemb, (size_t)B_ * DH * sizeof(float), cudaMemcpyDeviceToDevice);

    const int nt1 = (B_ / 256) * (DFF / 128);   // 512 tiles, nx=32
    const int nt2 = (B_ / 256) * (DH / 128);    // 128 tiles, nx=8

    float* hc = p_hA;
    float* hx = p_hB;
    for (int s = 0; s < STEPS; s++) {
        layernorm_split<<<B_, 256>>>(hc, ln_g, ln_b, p_hnhi, p_hnlo);
        gemm_f16x2<EPI_TANH><<<NSM, 256, GSMEM>>>(
            p_hnhi, p_hnlo, p_W1h, b1, DFF, DH, nt1, DFF / 128,
            nullptr, p_hidhi, p_hidlo, nullptr, nullptr, 0.f);
        gemm_f16x2<EPI_STEP><<<NSM, 256, GSMEM>>>(
            p_hidhi, p_hidlo, p_W2h, b2, DH, DFF, nt2, DH / 128,
            hx, nullptr, nullptr, hc, p_xemb, GAMMA_F);
        float* tmp = hc; hc = hx; hx = tmp;
    }

    // out = h @ head_w^T + head_b (fp32 SIMT)
    gemm_f32_bias<<<dim3(DOUT / BN, B_ / BM), 256>>>(hc, head_w, head_b, out, B_, DOUT, DH);
}

// round 10
// speedup vs baseline: 6.3826x; 1.7223x over previous
#include <cuda_runtime.h>
#include <cuda_fp16.h>
#include <math.h>
#include <cstddef>
#include <cstdint>

// ---------------- problem constants ----------------
#define B_    4096
#define DIN   512
#define DH    1024
#define DOUT  256
#define DFF   4096
#define STEPS 30
#define LN_EPSF 1e-5f
#define GAMMA_F 0.17677669529663687f   // 0.5*sqrt(64/512)
#define NSM   148

// ---------------- device scratch (no allocations allowed) ----------------
__device__ float g_xemb[(size_t)B_ * DH];
__device__ float g_hA[(size_t)B_ * DH];
__device__ float g_hB[(size_t)B_ * DH];
__device__ __half g_W1h[(size_t)DFF * DH];
__device__ __half g_W2h[(size_t)DH * DFF];
__device__ __half g_hn[(size_t)B_ * DH];
__device__ __half g_hid[(size_t)B_ * DFF];
__device__ float g_u[4096];
__device__ float g_v[4096];
__device__ float g_t[4096];
__device__ float g_sig[2];

// ---------------- low-level helpers (plain sm_80+ features only) ----------------
__device__ __forceinline__ uint32_t smem_u32(const void* p) {
    uint32_t a;
    asm("{ .reg .u64 t; cvta.to.shared.u64 t, %1; cvt.u32.u64 %0, t; }" : "=r"(a) : "l"(p));
    return a;
}
__device__ __forceinline__ void cp_async16(uint32_t dst, const void* src) {
    asm volatile("cp.async.cg.shared.global [%0], [%1], 16;" :: "r"(dst), "l"(src) : "memory");
}
__device__ __forceinline__ void cp_commit() {
    asm volatile("cp.async.commit_group;" ::: "memory");
}
template<int N> __device__ __forceinline__ void cp_wait() {
    asm volatile("cp.async.wait_group %0;" :: "n"(N) : "memory");
}
__device__ __forceinline__ void ldm_x4(uint32_t addr, uint32_t* r) {
    asm volatile("ldmatrix.sync.aligned.m8n8.x4.shared.b16 {%0,%1,%2,%3}, [%4];"
        : "=r"(r[0]), "=r"(r[1]), "=r"(r[2]), "=r"(r[3]) : "r"(addr));
}
// fp16 m16n8k16 MMA, fp32 accumulate
__device__ __forceinline__ void mma_f16(float* d, const uint32_t* a, const uint32_t* b) {
    asm volatile("mma.sync.aligned.m16n8k16.row.col.f32.f16.f16.f32 "
        "{%0,%1,%2,%3}, {%4,%5,%6,%7}, {%8,%9}, {%0,%1,%2,%3};"
        : "+f"(d[0]), "+f"(d[1]), "+f"(d[2]), "+f"(d[3])
        : "r"(a[0]), "r"(a[1]), "r"(a[2]), "r"(a[3]), "r"(b[0]), "r"(b[1]));
}
// swizzled offset inside a tile: row r (64B rows), 16B-chunk c (0..3)
__device__ __forceinline__ uint32_t sw_off(int r, int c) {
    return ((uint32_t)r << 6) + (uint32_t)((c ^ ((r >> 1) & 3)) << 4);
}

// ---------------- small kernels: spectral norm ----------------
__global__ void init_vec_kernel(float* v, int n, float val) {
    int i = blockIdx.x * blockDim.x + threadIdx.x;
    if (i < n) v[i] = val;
}

__global__ void matvec_rows(const float* __restrict__ W, const float* __restrict__ v,
                            float* __restrict__ y, int C) {
    int row = blockIdx.x;
    const float* Wr = W + (size_t)row * C;
    float acc = 0.f;
    for (int j = threadIdx.x; j < C; j += 256) acc += Wr[j] * v[j];
    __shared__ float sm[8];
    #pragma unroll
    for (int o = 16; o > 0; o >>= 1) acc += __shfl_down_sync(0xffffffffu, acc, o);
    if ((threadIdx.x & 31) == 0) sm[threadIdx.x >> 5] = acc;
    __syncthreads();
    if (threadIdx.x < 8) {
        float a = sm[threadIdx.x];
        #pragma unroll
        for (int o = 4; o > 0; o >>= 1) a += __shfl_down_sync(0xffu, a, o);
        if (threadIdx.x == 0) y[row] = a;
    }
}

// z[col] += partial dot(W[:,col], u); grid (C/32, 8); z must be zeroed first
__global__ void matvec_cols(const float* __restrict__ W, const float* __restrict__ u,
                            float* __restrict__ z, int R, int C) {
    int lane = threadIdx.x & 31;
    int rp   = threadIdx.x >> 5;
    int col  = blockIdx.x * 32 + lane;
    int rchunk = R >> 3;
    int r0 = blockIdx.y * rchunk;
    int r1 = r0 + rchunk;
    float acc = 0.f;
    for (int i = r0 + rp; i < r1; i += 8) acc += W[(size_t)i * C + col] * u[i];
    __shared__ float sm[8][33];
    sm[rp][lane] = acc;
    __syncthreads();
    if (rp == 0) {
        float a = 0.f;
        #pragma unroll
        for (int r = 0; r < 8; r++) a += sm[r][lane];
        atomicAdd(&z[col], a);
    }
}

__global__ void normalize_vec(float* v, int n) {
    __shared__ float sm[32];
    __shared__ float s_inv;
    float acc = 0.f;
    for (int i = threadIdx.x; i < n; i += 1024) { float x = v[i]; acc += x * x; }
    #pragma unroll
    for (int o = 16; o > 0; o >>= 1) acc += __shfl_down_sync(0xffffffffu, acc, o);
    if ((threadIdx.x & 31) == 0) sm[threadIdx.x >> 5] = acc;
    __syncthreads();
    if (threadIdx.x < 32) {
        float a = sm[threadIdx.x];
        #pragma unroll
        for (int o = 16; o > 0; o >>= 1) a = a + __shfl_down_sync(0xffffffffu, a, o);
        if (threadIdx.x == 0) s_inv = 1.0f / (sqrtf(a) + 1e-12f);
    }
    __syncthreads();
    float inv = s_inv;
    for (int i = threadIdx.x; i < n; i += 1024) v[i] *= inv;
}

__global__ void dot_kernel(const float* __restrict__ a, const float* __restrict__ b,
                           float* __restrict__ out, int n) {
    __shared__ float sm[32];
    float acc = 0.f;
    for (int i = threadIdx.x; i < n; i += 1024) acc += a[i] * b[i];
    #pragma unroll
    for (int o = 16; o > 0; o >>= 1) acc += __shfl_down_sync(0xffffffffu, acc, o);
    if ((threadIdx.x & 31) == 0) sm[threadIdx.x >> 5] = acc;
    __syncthreads();
    if (threadIdx.x < 32) {
        float a2 = sm[threadIdx.x];
        #pragma unroll
        for (int o = 16; o > 0; o >>= 1) a2 += __shfl_down_sync(0xffffffffu, a2, o);
        if (threadIdx.x == 0) out[0] = a2;
    }
}

// Wh = fp16(W / sigma)
__global__ void scale_half(const float* __restrict__ W, const float* __restrict__ sig,
                           __half* __restrict__ Wh, size_t n) {
    float inv = 1.0f / sig[0];
    size_t stride = (size_t)gridDim.x * blockDim.x;
    for (size_t i = (size_t)blockIdx.x * blockDim.x + threadIdx.x; i < n; i += stride)
        Wh[i] = __float2half_rn(W[i] * inv);
}

// ---------------- layernorm: fp32 in, fp16 out ----------------
__global__ void layernorm_half(const float* __restrict__ h,
                               const float* __restrict__ g, const float* __restrict__ b,
                               __half* __restrict__ o) {
    int row = blockIdx.x;
    const float* hr = h + (size_t)row * DH;
    float s = 0.f, ss = 0.f;
    float xl[4];
    #pragma unroll
    for (int t = 0; t < 4; t++) {
        float x = hr[threadIdx.x + t * 256];
        xl[t] = x; s += x; ss += x * x;
    }
    __shared__ float sm1[8], sm2[8];
    #pragma unroll
    for (int o2 = 16; o2 > 0; o2 >>= 1) {
        s  += __shfl_down_sync(0xffffffffu, s, o2);
        ss += __shfl_down_sync(0xffffffffu, ss, o2);
    }
    if ((threadIdx.x & 31) == 0) { sm1[threadIdx.x >> 5] = s; sm2[threadIdx.x >> 5] = ss; }
    __syncthreads();
    __shared__ float s_mu, s_inv;
    if (threadIdx.x < 8) {
        float a = sm1[threadIdx.x], c = sm2[threadIdx.x];
        #pragma unroll
        for (int o2 = 4; o2 > 0; o2 >>= 1) {
            a += __shfl_down_sync(0xffu, a, o2);
            c += __shfl_down_sync(0xffu, c, o2);
        }
        if (threadIdx.x == 0) {
            float mu  = a * (1.0f / DH);
            float var = c * (1.0f / DH) - mu * mu;
            s_mu = mu; s_inv = rsqrtf(var + LN_EPSF);
        }
    }
    __syncthreads();
    float mu = s_mu, inv = s_inv;
    #pragma unroll
    for (int t = 0; t < 4; t++) {
        int j = threadIdx.x + t * 256;
        float y = (xl[t] - mu) * inv * g[j] + b[j];
        o[(size_t)row * DH + j] = __float2half_rn(y);
    }
}

// ---------------- fp16 single-term persistent GEMM ----------------
// C[M,N] = A[M,K] @ (Wh[N,K])^T, both fp16, fp32 accumulate.
// CTA tile 256x128, 8 warps (4x2), warp tile 64x64 = 4x8 m16n8k16 frags.
// BK=32, 4-stage cp.async, 64B XOR-swizzled rows, persistent CTAs.
#define MSTAGES 4
#define ATILEB  (256 * 64)               // 16384 B: 256x32 fp16 tile
#define WTILEB  (128 * 64)               //  8192 B: 128x32 fp16 tile
#define STAGEB  (ATILEB + WTILEB)        // 24576 B
#define GSMEM   (MSTAGES * STAGEB)       // 98304 B

#define EPI_TANH 1
#define EPI_STEP 2

__device__ __forceinline__ void load_stage(
    uint32_t sbase, int buf, int k0,
    const __half* __restrict__ A, const __half* __restrict__ Wh,
    int bm, int bn, int K, int tid)
{
    uint32_t base = sbase + (uint32_t)buf * STAGEB;
    // A: 256 rows x 4 16B-chunks = 1024 lane-ops (4/thread)
    #pragma unroll
    for (int j = 0; j < 4; j++) {
        int c = tid + j * 256;                  // 0..1023
        int rr = c >> 2, c16 = c & 3;
        cp_async16(base + sw_off(rr, c16),
                   A + (size_t)(bm + rr) * K + k0 + c16 * 8);
    }
    // W: 128 rows x 4 chunks = 512 lane-ops (2/thread)
    #pragma unroll
    for (int j = 0; j < 2; j++) {
        int c = tid + j * 256;                  // 0..511
        int rr = c >> 2, c16 = c & 3;
        cp_async16(base + (uint32_t)ATILEB + sw_off(rr, c16),
                   Wh + (size_t)(bn + rr) * K + k0 + c16 * 8);
    }
}

template <int EPI>
__global__ __launch_bounds__(256, 1) void gemm_f16(
    const __half* __restrict__ A, const __half* __restrict__ Wh,
    const float* __restrict__ bias, int N, int K, int ntiles, int nx,
    float* __restrict__ Cf, __half* __restrict__ Ch,
    const float* __restrict__ hprev, const float* __restrict__ xemb, float gamma) {

    extern __shared__ __align__(128) char smem[];
    uint32_t sb = smem_u32(smem);
    int tid = threadIdx.x, wid = tid >> 5, lane = tid & 31;
    int m0 = (wid >> 1) * 64, n0 = (wid & 1) * 64;   // warp tile 64x64
    int r16 = lane & 15, kh = lane >> 4;
    int g8 = lane >> 3, l8 = lane & 7;
    int qr = lane >> 2, qc = (lane & 3) * 2;
    const int nch = K >> 5;

    for (int tile = blockIdx.x; tile < ntiles; tile += gridDim.x) {
        int bm = (tile / nx) * 256, bn = (tile % nx) * 128;

        float acc[4][8][4] = {};

        #pragma unroll
        for (int s = 0; s < MSTAGES - 1; s++) {
            load_stage(sb, s, s << 5, A, Wh, bm, bn, K, tid);
            cp_commit();
        }

        for (int i = 0; i < nch; i++) {
            cp_wait<MSTAGES - 2>();
            __syncthreads();

            uint32_t st = sb + (uint32_t)(i & (MSTAGES - 1)) * STAGEB;
            #pragma unroll
            for (int ks = 0; ks < 2; ks++) {
                uint32_t a[4][4], w[4][4];
                #pragma unroll
                for (int mt = 0; mt < 4; mt++)
                    ldm_x4(st + sw_off(m0 + mt * 16 + r16, ks * 2 + kh), a[mt]);
                #pragma unroll
                for (int nh = 0; nh < 4; nh++)
                    ldm_x4(st + ATILEB +
                           sw_off(n0 + nh * 16 + (g8 >> 1) * 8 + l8, ks * 2 + (g8 & 1)),
                           w[nh]);
                #pragma unroll
                for (int mt = 0; mt < 4; mt++)
                    #pragma unroll
                    for (int nt = 0; nt < 8; nt++)
                        mma_f16(acc[mt][nt], a[mt], &w[nt >> 1][(nt & 1) * 2]);
            }

            int nxt = i + MSTAGES - 1;
            if (nxt < nch)
                load_stage(sb, nxt & (MSTAGES - 1), nxt << 5, A, Wh, bm, bn, K, tid);
            cp_commit();
        }

        // epilogue from accumulator registers
        #pragma unroll
        for (int mt = 0; mt < 4; mt++) {
            #pragma unroll
            for (int nt = 0; nt < 8; nt++) {
                int c0 = bn + n0 + nt * 8 + qc;
                float2 bz = *(const float2*)(bias + c0);
                #pragma unroll
                for (int h = 0; h < 2; h++) {
                    int r = bm + m0 + mt * 16 + qr + h * 8;
                    float v0 = acc[mt][nt][h * 2 + 0] + bz.x;
                    float v1 = acc[mt][nt][h * 2 + 1] + bz.y;
                    size_t idx = (size_t)r * N + c0;
                    if (EPI == EPI_TANH) {
                        __half2 hp;
                        hp.x = __float2half_rn(tanhf(v0));
                        hp.y = __float2half_rn(tanhf(v1));
                        *(__half2*)(Ch + idx) = hp;
                    } else {
                        float2 hp = *(const float2*)(hprev + idx);
                        float2 xe = *(const float2*)(xemb + idx);
                        float2 o;
                        o.x = (1.0f - gamma) * hp.x + gamma * (v0 + xe.x);
                        o.y = (1.0f - gamma) * hp.y + gamma * (v1 + xe.y);
                        *(float2*)(Cf + idx) = o;
                    }
                }
            }
        }
        __syncthreads();   // protect smem buffers before next tile's prologue
    }
}

// ---------------- fp32 SIMT GEMM (embed + head only) ----------------
#define BM 128
#define BN 128
#define BK 8
#define TM 8
#define TN 8

__global__ __launch_bounds__(256, 2) void gemm_f32_bias(
    const float* __restrict__ A, const float* __restrict__ W,
    const float* __restrict__ bias, float* __restrict__ C,
    int M, int N, int K) {

    __shared__ __align__(16) float As[BK][BM];
    __shared__ __align__(16) float Ws[BK][BN];

    int tid = threadIdx.x;
    int bm = blockIdx.y * BM, bn = blockIdx.x * BN;
    const float* Ablk = A + (size_t)bm * K;
    const float* Wblk = W + (size_t)bn * K;

    int lrow = tid >> 1;
    int lcol = (tid & 1) * 4;
    int ty = tid >> 4, tx = tid & 15;

    float acc[TM][TN] = {};

    for (int k0 = 0; k0 < K; k0 += BK) {
        float4 a4 = *reinterpret_cast<const float4*>(Ablk + (size_t)lrow * K + k0 + lcol);
        float4 w4 = *reinterpret_cast<const float4*>(Wblk + (size_t)lrow * K + k0 + lcol);
        As[lcol + 0][lrow] = a4.x; As[lcol + 1][lrow] = a4.y;
        As[lcol + 2][lrow] = a4.z; As[lcol + 3][lrow] = a4.w;
        Ws[lcol + 0][lrow] = w4.x; Ws[lcol + 1][lrow] = w4.y;
        Ws[lcol + 2][lrow] = w4.z; Ws[lcol + 3][lrow] = w4.w;
        __syncthreads();
        #pragma unroll
        for (int k = 0; k < BK; k++) {
            float4 a0 = *reinterpret_cast<const float4*>(&As[k][ty * TM]);
            float4 a1 = *reinterpret_cast<const float4*>(&As[k][ty * TM + 4]);
            float4 w0 = *reinterpret_cast<const float4*>(&Ws[k][tx * TN]);
            float4 w1 = *reinterpret_cast<const float4*>(&Ws[k][tx * TN + 4]);
            float ra[TM] = {a0.x, a0.y, a0.z, a0.w, a1.x, a1.y, a1.z, a1.w};
            float rw[TN] = {w0.x, w0.y, w0.z, w0.w, w1.x, w1.y, w1.z, w1.w};
            #pragma unroll
            for (int i = 0; i < TM; i++)
                #pragma unroll
                for (int j = 0; j < TN; j++)
                    acc[i][j] += ra[i] * rw[j];
        }
        __syncthreads();
    }

    #pragma unroll
    for (int i = 0; i < TM; i++) {
        int m = bm + ty * TM + i;
        #pragma unroll
        for (int j = 0; j < TN; j++) {
            int n = bn + tx * TN + j;
            C[(size_t)m * N + n] = acc[i][j] + bias[n];
        }
    }
}

// ---------------- host-side helpers ----------------
static void spectral_sigma(const float* W, int R, int C,
                           float* u, float* v, float* t, float* sig) {
    float v0 = 1.0f / sqrtf((float)C);
    init_vec_kernel<<<(C + 255) / 256, 256>>>(v, C, v0);
    for (int it = 0; it < 15; it++) {
        matvec_rows<<<R, 256>>>(W, v, u, C);
        normalize_vec<<<1, 1024>>>(u, R);
        init_vec_kernel<<<(C + 255) / 256, 256>>>(v, C, 0.f);
        matvec_cols<<<dim3(C / 32, 8), 256>>>(W, u, v, R, C);
        normalize_vec<<<1, 1024>>>(v, C);
    }
    matvec_rows<<<R, 256>>>(W, v, t, C);
    dot_kernel<<<1, 1024>>>(u, t, sig, R);
}

extern "C" void kernel_launch(void* const* d_in, const int* in_sizes, int n_in,
                              void* d_out, int out_size) {
    const float* x       = (const float*)d_in[0];
    const float* embed_w = (const float*)d_in[1];
    const float* embed_b = (const float*)d_in[2];
    const float* W1      = (const float*)d_in[3];
    const float* b1      = (const float*)d_in[4];
    const float* W2      = (const float*)d_in[5];
    const float* b2      = (const float*)d_in[6];
    const float* ln_g    = (const float*)d_in[7];
    const float* ln_b    = (const float*)d_in[8];
    const float* head_w  = (const float*)d_in[9];
    const float* head_b  = (const float*)d_in[10];
    float* out = (float*)d_out;

    float *p_xemb, *p_hA, *p_hB, *p_u, *p_v, *p_t, *p_sig;
    __half *p_W1h, *p_W2h, *p_hn, *p_hid;
    cudaGetSymbolAddress((void**)&p_xemb, g_xemb);
    cudaGetSymbolAddress((void**)&p_hA, g_hA);
    cudaGetSymbolAddress((void**)&p_hB, g_hB);
    cudaGetSymbolAddress((void**)&p_u, g_u);
    cudaGetSymbolAddress((void**)&p_v, g_v);
    cudaGetSymbolAddress((void**)&p_t, g_t);
    cudaGetSymbolAddress((void**)&p_sig, g_sig);
    cudaGetSymbolAddress((void**)&p_W1h, g_W1h);
    cudaGetSymbolAddress((void**)&p_W2h, g_W2h);
    cudaGetSymbolAddress((void**)&p_hn, g_hn);
    cudaGetSymbolAddress((void**)&p_hid, g_hid);

    cudaFuncSetAttribute(gemm_f16<EPI_TANH>,
                         cudaFuncAttributeMaxDynamicSharedMemorySize, GSMEM);
    cudaFuncSetAttribute(gemm_f16<EPI_STEP>,
                         cudaFuncAttributeMaxDynamicSharedMemorySize, GSMEM);

    // spectral sigma + fp16 weights
    spectral_sigma(W1, DFF, DH, p_u, p_v, p_t, p_sig);
    scale_half<<<2048, 256>>>(W1, p_sig, p_W1h, (size_t)DFF * DH);
    spectral_sigma(W2, DH, DFF, p_u, p_v, p_t, p_sig);
    scale_half<<<2048, 256>>>(W2, p_sig, p_W2h, (size_t)DH * DFF);

    // x_emb = x @ embed_w^T + embed_b  (fp32 SIMT)
    gemm_f32_bias<<<dim3(DH / BN, B_ / BM), 256>>>(x, embed_w, embed_b, p_xemb, B_, DH, DIN);

    // h0 = x_emb
    cudaMemcpyAsync(p_hA, p_xemb, (size_t)B_ * DH * sizeof(float), cudaMemcpyDeviceToDevice);

    const int nt1 = (B_ / 256) * (DFF / 128);   // 512 tiles, nx=32
    const int nt2 = (B_ / 256) * (DH / 128);    // 128 tiles, nx=8

    float* hc = p_hA;
    float* hx = p_hB;
    for (int s = 0; s < STEPS; s++) {
        layernorm_half<<<B_, 256>>>(hc, ln_g, ln_b, p_hn);
        gemm_f16<EPI_TANH><<<NSM, 256, GSMEM>>>(
            p_hn, p_W1h, b1, DFF, DH, nt1, DFF / 128,
            nullptr, p_hid, nullptr, nullptr, 0.f);
        gemm_f16<EPI_STEP><<<NSM, 256, GSMEM>>>(
            p_hid, p_W2h, b2, DH, DFF, nt2, DH / 128,
            hx, nullptr, hc, p_xemb, GAMMA_F);
        float* tmp = hc; hc = hx; hx = tmp;
    }

    // out = h @ head_w^T + head_b (fp32 SIMT)
    gemm_f32_bias<<<dim3(DOUT / BN, B_ / BM), 256>>>(hc, head_w, head_b, out, B_, DOUT, DH);
}

// round 11
// speedup vs baseline: 6.5257x; 1.0224x over previous
#include <cuda_runtime.h>
#include <cuda_fp16.h>
#include <math.h>
#include <cstddef>
#include <cstdint>

// ---------------- problem constants ----------------
#define B_    4096
#define DIN   512
#define DH    1024
#define DOUT  256
#define DFF   4096
#define STEPS 30
#define LN_EPSF 1e-5f
#define GAMMA_F 0.17677669529663687f   // 0.5*sqrt(64/512)
#define NSM   148

// ---------------- device scratch (no allocations allowed) ----------------
__device__ float g_xemb[(size_t)B_ * DH];
__device__ float g_hA[(size_t)B_ * DH];
__device__ float g_hB[(size_t)B_ * DH];
__device__ __half g_W1h[(size_t)DFF * DH];
__device__ __half g_W2h[(size_t)DH * DFF];
__device__ __half g_hn[(size_t)B_ * DH];
__device__ __half g_hid[(size_t)B_ * DFF];
__device__ float g_u[4096];
__device__ float g_v0[4096];
__device__ float g_v1[4096];
__device__ float g_t[4096];
__device__ float g_sig[2];

// ---------------- low-level helpers (plain sm_80+ features only) ----------------
__device__ __forceinline__ uint32_t smem_u32(const void* p) {
    uint32_t a;
    asm("{ .reg .u64 t; cvta.to.shared.u64 t, %1; cvt.u32.u64 %0, t; }" : "=r"(a) : "l"(p));
    return a;
}
__device__ __forceinline__ void cp_async16(uint32_t dst, const void* src) {
    asm volatile("cp.async.cg.shared.global [%0], [%1], 16;" :: "r"(dst), "l"(src) : "memory");
}
__device__ __forceinline__ void cp_commit() {
    asm volatile("cp.async.commit_group;" ::: "memory");
}
template<int N> __device__ __forceinline__ void cp_wait() {
    asm volatile("cp.async.wait_group %0;" :: "n"(N) : "memory");
}
__device__ __forceinline__ void ldm_x4(uint32_t addr, uint32_t* r) {
    asm volatile("ldmatrix.sync.aligned.m8n8.x4.shared.b16 {%0,%1,%2,%3}, [%4];"
        : "=r"(r[0]), "=r"(r[1]), "=r"(r[2]), "=r"(r[3]) : "r"(addr));
}
// fp16 m16n8k16 MMA, fp32 accumulate
__device__ __forceinline__ void mma_f16(float* d, const uint32_t* a, const uint32_t* b) {
    asm volatile("mma.sync.aligned.m16n8k16.row.col.f32.f16.f16.f32 "
        "{%0,%1,%2,%3}, {%4,%5,%6,%7}, {%8,%9}, {%0,%1,%2,%3};"
        : "+f"(d[0]), "+f"(d[1]), "+f"(d[2]), "+f"(d[3])
        : "r"(a[0]), "r"(a[1]), "r"(a[2]), "r"(a[3]), "r"(b[0]), "r"(b[1]));
}
// swizzled offset inside a tile: row r (64B rows), 16B-chunk c (0..3)
__device__ __forceinline__ uint32_t sw_off(int r, int c) {
    return ((uint32_t)r << 6) + (uint32_t)((c ^ ((r >> 1) & 3)) << 4);
}

// ---------------- small kernels: spectral norm ----------------
__global__ void init_vec_kernel(float* v, int n, float val) {
    int i = blockIdx.x * blockDim.x + threadIdx.x;
    if (i < n) v[i] = val;
}

// y[row] = dot(W[row,:], v); optionally zeros zout[0..nz) as a side job.
__global__ void matvec_rows(const float* __restrict__ W, const float* __restrict__ v,
                            float* __restrict__ y, int C,
                            float* __restrict__ zout, int nz) {
    if (zout) {
        int gi = blockIdx.x * blockDim.x + threadIdx.x;
        if (gi < nz) zout[gi] = 0.f;
    }
    int row = blockIdx.x;
    const float* Wr = W + (size_t)row * C;
    float acc = 0.f;
    for (int j = threadIdx.x; j < C; j += 256) acc += Wr[j] * v[j];
    __shared__ float sm[8];
    #pragma unroll
    for (int o = 16; o > 0; o >>= 1) acc += __shfl_down_sync(0xffffffffu, acc, o);
    if ((threadIdx.x & 31) == 0) sm[threadIdx.x >> 5] = acc;
    __syncthreads();
    if (threadIdx.x < 8) {
        float a = sm[threadIdx.x];
        #pragma unroll
        for (int o = 4; o > 0; o >>= 1) a += __shfl_down_sync(0xffu, a, o);
        if (threadIdx.x == 0) y[row] = a;
    }
}

// z[col] += partial dot(W[:,col], u); grid (C/32, 8); z must be zeroed first
__global__ void matvec_cols(const float* __restrict__ W, const float* __restrict__ u,
                            float* __restrict__ z, int R, int C) {
    int lane = threadIdx.x & 31;
    int rp   = threadIdx.x >> 5;
    int col  = blockIdx.x * 32 + lane;
    int rchunk = R >> 3;
    int r0 = blockIdx.y * rchunk;
    int r1 = r0 + rchunk;
    float acc = 0.f;
    for (int i = r0 + rp; i < r1; i += 8) acc += W[(size_t)i * C + col] * u[i];
    __shared__ float sm[8][33];
    sm[rp][lane] = acc;
    __syncthreads();
    if (rp == 0) {
        float a = 0.f;
        #pragma unroll
        for (int r = 0; r < 8; r++) a += sm[r][lane];
        atomicAdd(&z[col], a);
    }
}

// sigma = (u . t) / (||u|| * ||v||); single 1024-thread block.
__global__ void finalize_sigma(const float* __restrict__ u, const float* __restrict__ t,
                               const float* __restrict__ v, int R, int C,
                               float* __restrict__ sig) {
    float du = 0.f, nu = 0.f, nv = 0.f;
    for (int i = threadIdx.x; i < R; i += 1024) {
        float ui = u[i];
        du += ui * t[i];
        nu += ui * ui;
    }
    for (int i = threadIdx.x; i < C; i += 1024) {
        float vi = v[i];
        nv += vi * vi;
    }
    __shared__ float s1[32], s2[32], s3[32];
    #pragma unroll
    for (int o = 16; o > 0; o >>= 1) {
        du += __shfl_down_sync(0xffffffffu, du, o);
        nu += __shfl_down_sync(0xffffffffu, nu, o);
        nv += __shfl_down_sync(0xffffffffu, nv, o);
    }
    if ((threadIdx.x & 31) == 0) {
        s1[threadIdx.x >> 5] = du; s2[threadIdx.x >> 5] = nu; s3[threadIdx.x >> 5] = nv;
    }
    __syncthreads();
    if (threadIdx.x < 32) {
        float a = s1[threadIdx.x], b = s2[threadIdx.x], c = s3[threadIdx.x];
        #pragma unroll
        for (int o = 16; o > 0; o >>= 1) {
            a += __shfl_down_sync(0xffffffffu, a, o);
            b += __shfl_down_sync(0xffffffffu, b, o);
            c += __shfl_down_sync(0xffffffffu, c, o);
        }
        if (threadIdx.x == 0)
            sig[0] = a / (sqrtf(b) * sqrtf(c) + 1e-12f);
    }
}

// Wh = fp16(W / sigma)
__global__ void scale_half(const float* __restrict__ W, const float* __restrict__ sig,
                           __half* __restrict__ Wh, size_t n) {
    float inv = 1.0f / sig[0];
    size_t stride = (size_t)gridDim.x * blockDim.x;
    for (size_t i = (size_t)blockIdx.x * blockDim.x + threadIdx.x; i < n; i += stride)
        Wh[i] = __float2half_rn(W[i] * inv);
}

// ---------------- layernorm: fp32 in, fp16 out ----------------
__global__ void layernorm_half(const float* __restrict__ h,
                               const float* __restrict__ g, const float* __restrict__ b,
                               __half* __restrict__ o) {
    int row = blockIdx.x;
    const float* hr = h + (size_t)row * DH;
    float s = 0.f, ss = 0.f;
    float xl[4];
    #pragma unroll
    for (int t = 0; t < 4; t++) {
        float x = hr[threadIdx.x + t * 256];
        xl[t] = x; s += x; ss += x * x;
    }
    __shared__ float sm1[8], sm2[8];
    #pragma unroll
    for (int o2 = 16; o2 > 0; o2 >>= 1) {
        s  += __shfl_down_sync(0xffffffffu, s, o2);
        ss += __shfl_down_sync(0xffffffffu, ss, o2);
    }
    if ((threadIdx.x & 31) == 0) { sm1[threadIdx.x >> 5] = s; sm2[threadIdx.x >> 5] = ss; }
    __syncthreads();
    __shared__ float s_mu, s_inv;
    if (threadIdx.x < 8) {
        float a = sm1[threadIdx.x], c = sm2[threadIdx.x];
        #pragma unroll
        for (int o2 = 4; o2 > 0; o2 >>= 1) {
            a += __shfl_down_sync(0xffu, a, o2);
            c += __shfl_down_sync(0xffu, c, o2);
        }
        if (threadIdx.x == 0) {
            float mu  = a * (1.0f / DH);
            float var = c * (1.0f / DH) - mu * mu;
            s_mu = mu; s_inv = rsqrtf(var + LN_EPSF);
        }
    }
    __syncthreads();
    float mu = s_mu, inv = s_inv;
    #pragma unroll
    for (int t = 0; t < 4; t++) {
        int j = threadIdx.x + t * 256;
        float y = (xl[t] - mu) * inv * g[j] + b[j];
        o[(size_t)row * DH + j] = __float2half_rn(y);
    }
}

// ---------------- fp16 single-term persistent GEMM ----------------
// C[M,N] = A[M,K] @ (Wh[N,K])^T, both fp16, fp32 accumulate.
// CTA tile 256x128, 8 warps (4x2), warp tile 64x64 = 4x8 m16n8k16 frags.
// BK=32, 4-stage cp.async, 64B XOR-swizzled rows, persistent CTAs.
#define MSTAGES 4
#define ATILEB  (256 * 64)               // 16384 B: 256x32 fp16 tile
#define WTILEB  (128 * 64)               //  8192 B: 128x32 fp16 tile
#define STAGEB  (ATILEB + WTILEB)        // 24576 B
#define GSMEM   (MSTAGES * STAGEB)       // 98304 B

#define EPI_TANH 1
#define EPI_STEP 2

__device__ __forceinline__ void load_stage(
    uint32_t sbase, int buf, int k0,
    const __half* __restrict__ A, const __half* __restrict__ Wh,
    int bm, int bn, int K, int tid)
{
    uint32_t base = sbase + (uint32_t)buf * STAGEB;
    // A: 256 rows x 4 16B-chunks = 1024 lane-ops (4/thread)
    #pragma unroll
    for (int j = 0; j < 4; j++) {
        int c = tid + j * 256;                  // 0..1023
        int rr = c >> 2, c16 = c & 3;
        cp_async16(base + sw_off(rr, c16),
                   A + (size_t)(bm + rr) * K + k0 + c16 * 8);
    }
    // W: 128 rows x 4 chunks = 512 lane-ops (2/thread)
    #pragma unroll
    for (int j = 0; j < 2; j++) {
        int c = tid + j * 256;                  // 0..511
        int rr = c >> 2, c16 = c & 3;
        cp_async16(base + (uint32_t)ATILEB + sw_off(rr, c16),
                   Wh + (size_t)(bn + rr) * K + k0 + c16 * 8);
    }
}

template <int EPI>
__global__ __launch_bounds__(256, 1) void gemm_f16(
    const __half* __restrict__ A, const __half* __restrict__ Wh,
    const float* __restrict__ bias, int N, int K, int ntiles, int nx,
    float* __restrict__ Cf, __half* __restrict__ Ch,
    const float* __restrict__ hprev, const float* __restrict__ xemb, float gamma) {

    extern __shared__ __align__(128) char smem[];
    uint32_t sb = smem_u32(smem);
    int tid = threadIdx.x, wid = tid >> 5, lane = tid & 31;
    int m0 = (wid >> 1) * 64, n0 = (wid & 1) * 64;   // warp tile 64x64
    int r16 = lane & 15, kh = lane >> 4;
    int g8 = lane >> 3, l8 = lane & 7;
    int qr = lane >> 2, qc = (lane & 3) * 2;
    const int nch = K >> 5;

    for (int tile = blockIdx.x; tile < ntiles; tile += gridDim.x) {
        int bm = (tile / nx) * 256, bn = (tile % nx) * 128;

        float acc[4][8][4] = {};

        #pragma unroll
        for (int s = 0; s < MSTAGES - 1; s++) {
            load_stage(sb, s, s << 5, A, Wh, bm, bn, K, tid);
            cp_commit();
        }

        for (int i = 0; i < nch; i++) {
            cp_wait<MSTAGES - 2>();
            __syncthreads();

            uint32_t st = sb + (uint32_t)(i & (MSTAGES - 1)) * STAGEB;
            #pragma unroll
            for (int ks = 0; ks < 2; ks++) {
                uint32_t a[4][4], w[4][4];
                #pragma unroll
                for (int mt = 0; mt < 4; mt++)
                    ldm_x4(st + sw_off(m0 + mt * 16 + r16, ks * 2 + kh), a[mt]);
                #pragma unroll
                for (int nh = 0; nh < 4; nh++)
                    ldm_x4(st + ATILEB +
                           sw_off(n0 + nh * 16 + (g8 >> 1) * 8 + l8, ks * 2 + (g8 & 1)),
                           w[nh]);
                #pragma unroll
                for (int mt = 0; mt < 4; mt++)
                    #pragma unroll
                    for (int nt = 0; nt < 8; nt++)
                        mma_f16(acc[mt][nt], a[mt], &w[nt >> 1][(nt & 1) * 2]);
            }

            int nxt = i + MSTAGES - 1;
            if (nxt < nch)
                load_stage(sb, nxt & (MSTAGES - 1), nxt << 5, A, Wh, bm, bn, K, tid);
            cp_commit();
        }

        // epilogue from accumulator registers
        #pragma unroll
        for (int mt = 0; mt < 4; mt++) {
            #pragma unroll
            for (int nt = 0; nt < 8; nt++) {
                int c0 = bn + n0 + nt * 8 + qc;
                float2 bz = *(const float2*)(bias + c0);
                #pragma unroll
                for (int h = 0; h < 2; h++) {
                    int r = bm + m0 + mt * 16 + qr + h * 8;
                    float v0 = acc[mt][nt][h * 2 + 0] + bz.x;
                    float v1 = acc[mt][nt][h * 2 + 1] + bz.y;
                    size_t idx = (size_t)r * N + c0;
                    if (EPI == EPI_TANH) {
                        __half2 hp;
                        hp.x = __float2half_rn(tanhf(v0));
                        hp.y = __float2half_rn(tanhf(v1));
                        *(__half2*)(Ch + idx) = hp;
                    } else {
                        float2 hp = *(const float2*)(hprev + idx);
                        float2 xe = *(const float2*)(xemb + idx);
                        float2 o;
                        o.x = (1.0f - gamma) * hp.x + gamma * (v0 + xe.x);
                        o.y = (1.0f - gamma) * hp.y + gamma * (v1 + xe.y);
                        *(float2*)(Cf + idx) = o;
                    }
                }
            }
        }
        __syncthreads();   // protect smem buffers before next tile's prologue
    }
}

// ---------------- fp32 SIMT GEMM (embed + head only) ----------------
#define BM 128
#define BN 128
#define BK 8
#define TM 8
#define TN 8

__global__ __launch_bounds__(256, 2) void gemm_f32_bias(
    const float* __restrict__ A, const float* __restrict__ W,
    const float* __restrict__ bias, float* __restrict__ C,
    int M, int N, int K) {

    __shared__ __align__(16) float As[BK][BM];
    __shared__ __align__(16) float Ws[BK][BN];

    int tid = threadIdx.x;
    int bm = blockIdx.y * BM, bn = blockIdx.x * BN;
    const float* Ablk = A + (size_t)bm * K;
    const float* Wblk = W + (size_t)bn * K;

    int lrow = tid >> 1;
    int lcol = (tid & 1) * 4;
    int ty = tid >> 4, tx = tid & 15;

    float acc[TM][TN] = {};

    for (int k0 = 0; k0 < K; k0 += BK) {
        float4 a4 = *reinterpret_cast<const float4*>(Ablk + (size_t)lrow * K + k0 + lcol);
        float4 w4 = *reinterpret_cast<const float4*>(Wblk + (size_t)lrow * K + k0 + lcol);
        As[lcol + 0][lrow] = a4.x; As[lcol + 1][lrow] = a4.y;
        As[lcol + 2][lrow] = a4.z; As[lcol + 3][lrow] = a4.w;
        Ws[lcol + 0][lrow] = w4.x; Ws[lcol + 1][lrow] = w4.y;
        Ws[lcol + 2][lrow] = w4.z; Ws[lcol + 3][lrow] = w4.w;
        __syncthreads();
        #pragma unroll
        for (int k = 0; k < BK; k++) {
            float4 a0 = *reinterpret_cast<const float4*>(&As[k][ty * TM]);
            float4 a1 = *reinterpret_cast<const float4*>(&As[k][ty * TM + 4]);
            float4 w0 = *reinterpret_cast<const float4*>(&Ws[k][tx * TN]);
            float4 w1 = *reinterpret_cast<const float4*>(&Ws[k][tx * TN + 4]);
            float ra[TM] = {a0.x, a0.y, a0.z, a0.w, a1.x, a1.y, a1.z, a1.w};
            float rw[TN] = {w0.x, w0.y, w0.z, w0.w, w1.x, w1.y, w1.z, w1.w};
            #pragma unroll
            for (int i = 0; i < TM; i++)
                #pragma unroll
                for (int j = 0; j < TN; j++)
                    acc[i][j] += ra[i] * rw[j];
        }
        __syncthreads();
    }

    #pragma unroll
    for (int i = 0; i < TM; i++) {
        int m = bm + ty * TM + i;
        #pragma unroll
        for (int j = 0; j < TN; j++) {
            int n = bn + tx * TN + j;
            C[(size_t)m * N + n] = acc[i][j] + bias[n];
        }
    }
}

// ---------------- host-side helpers ----------------
// Unnormalized power iteration (scale-invariant); sigma assembled at the end.
static void spectral_sigma(const float* W, int R, int C,
                           float* u, float* va, float* vb, float* t, float* sig) {
    float v0 = 1.0f / sqrtf((float)C);
    init_vec_kernel<<<(C + 255) / 256, 256>>>(va, C, v0);
    float* cur = va;
    float* oth = vb;
    for (int it = 0; it < 15; it++) {
        // u = W * cur (and zero oth for the accumulation below)
        matvec_rows<<<R, 256>>>(W, cur, u, C, oth, C);
        // oth += W^T * u
        matvec_cols<<<dim3(C / 32, 8), 256>>>(W, u, oth, R, C);
        float* tmp = cur; cur = oth; oth = tmp;
    }
    // t = W * v_raw ; sigma = (u.t) / (||u|| ||v||)
    matvec_rows<<<R, 256>>>(W, cur, t, C, nullptr, 0);
    finalize_sigma<<<1, 1024>>>(u, t, cur, R, C, sig);
}

extern "C" void kernel_launch(void* const* d_in, const int* in_sizes, int n_in,
                              void* d_out, int out_size) {
    const float* x       = (const float*)d_in[0];
    const float* embed_w = (const float*)d_in[1];
    const float* embed_b = (const float*)d_in[2];
    const float* W1      = (const float*)d_in[3];
    const float* b1      = (const float*)d_in[4];
    const float* W2      = (const float*)d_in[5];
    const float* b2      = (const float*)d_in[6];
    const float* ln_g    = (const float*)d_in[7];
    const float* ln_b    = (const float*)d_in[8];
    const float* head_w  = (const float*)d_in[9];
    const float* head_b  = (const float*)d_in[10];
    float* out = (float*)d_out;

    float *p_xemb, *p_hA, *p_hB, *p_u, *p_v0, *p_v1, *p_t, *p_sig;
    __half *p_W1h, *p_W2h, *p_hn, *p_hid;
    cudaGetSymbolAddress((void**)&p_xemb, g_xemb);
    cudaGetSymbolAddress((void**)&p_hA, g_hA);
    cudaGetSymbolAddress((void**)&p_hB, g_hB);
    cudaGetSymbolAddress((void**)&p_u, g_u);
    cudaGetSymbolAddress((void**)&p_v0, g_v0);
    cudaGetSymbolAddress((void**)&p_v1, g_v1);
    cudaGetSymbolAddress((void**)&p_t, g_t);
    cudaGetSymbolAddress((void**)&p_sig, g_sig);
    cudaGetSymbolAddress((void**)&p_W1h, g_W1h);
    cudaGetSymbolAddress((void**)&p_W2h, g_W2h);
    cudaGetSymbolAddress((void**)&p_hn, g_hn);
    cudaGetSymbolAddress((void**)&p_hid, g_hid);

    cudaFuncSetAttribute(gemm_f16<EPI_TANH>,
                         cudaFuncAttributeMaxDynamicSharedMemorySize, GSMEM);
    cudaFuncSetAttribute(gemm_f16<EPI_STEP>,
                         cudaFuncAttributeMaxDynamicSharedMemorySize, GSMEM);

    // spectral sigma + fp16 weights
    spectral_sigma(W1, DFF, DH, p_u, p_v0, p_v1, p_t, p_sig);
    scale_half<<<2048, 256>>>(W1, p_sig, p_W1h, (size_t)DFF * DH);
    spectral_sigma(W2, DH, DFF, p_u, p_v0, p_v1, p_t, p_sig + 1);
    scale_half<<<2048, 256>>>(W2, p_sig + 1, p_W2h, (size_t)DH * DFF);

    // x_emb = x @ embed_w^T + embed_b  (fp32 SIMT)
    gemm_f32_bias<<<dim3(DH / BN, B_ / BM), 256>>>(x, embed_w, embed_b, p_xemb, B_, DH, DIN);

    // h0 = x_emb
    cudaMemcpyAsync(p_hA, p_xemb, (size_t)B_ * DH * sizeof(float), cudaMemcpyDeviceToDevice);

    const int nt1 = (B_ / 256) * (DFF / 128);   // 512 tiles, nx=32
    const int nt2 = (B_ / 256) * (DH / 128);    // 128 tiles, nx=8

    float* hc = p_hA;
    float* hx = p_hB;
    for (int s = 0; s < STEPS; s++) {
        layernorm_half<<<B_, 256>>>(hc, ln_g, ln_b, p_hn);
        gemm_f16<EPI_TANH><<<NSM, 256, GSMEM>>>(
            p_hn, p_W1h, b1, DFF, DH, nt1, DFF / 128,
            nullptr, p_hid, nullptr, nullptr, 0.f);
        gemm_f16<EPI_STEP><<<NSM, 256, GSMEM>>>(
            p_hid, p_W2h, b2, DH, DFF, nt2, DH / 128,
            hx, nullptr, hc, p_xemb, GAMMA_F);
        float* tmp = hc; hc = hx; hx = tmp;
    }

    // out = h @ head_w^T + head_b (fp32 SIMT)
    gemm_f32_bias<<<dim3(DOUT / BN, B_ / BM), 256>>>(hc, head_w, head_b, out, B_, DOUT, DH);
}

// round 12
// speedup vs baseline: 6.6813x; 1.0239x over previous
#include <cuda_runtime.h>
#include <cuda_fp16.h>
#include <math.h>
#include <cstddef>
#include <cstdint>

// ---------------- problem constants ----------------
#define B_    4096
#define DIN   512
#define DH    1024
#define DOUT  256
#define DFF   4096
#define STEPS 30
#define LN_EPSF 1e-5f
#define GAMMA_F 0.17677669529663687f   // 0.5*sqrt(64/512)
#define NSM   148

// ---------------- device scratch (no allocations allowed) ----------------
__device__ float g_xemb[(size_t)B_ * DH];
__device__ float g_hA[(size_t)B_ * DH];
__device__ float g_hB[(size_t)B_ * DH];
__device__ __half g_W1h[(size_t)DFF * DH];
__device__ __half g_W2h[(size_t)DH * DFF];
__device__ __half g_hn[(size_t)B_ * DH];
__device__ __half g_hid[(size_t)B_ * DFF];
__device__ float g_u[4096];
__device__ float g_v0[4096];
__device__ float g_v1[4096];
__device__ float g_t[4096];
__device__ float g_sig[2];

// ---------------- low-level helpers (plain sm_80+ features only) ----------------
__device__ __forceinline__ uint32_t smem_u32(const void* p) {
    uint32_t a;
    asm("{ .reg .u64 t; cvta.to.shared.u64 t, %1; cvt.u32.u64 %0, t; }" : "=r"(a) : "l"(p));
    return a;
}
__device__ __forceinline__ void cp_async16(uint32_t dst, const void* src) {
    asm volatile("cp.async.cg.shared.global [%0], [%1], 16;" :: "r"(dst), "l"(src) : "memory");
}
__device__ __forceinline__ void cp_commit() {
    asm volatile("cp.async.commit_group;" ::: "memory");
}
template<int N> __device__ __forceinline__ void cp_wait() {
    asm volatile("cp.async.wait_group %0;" :: "n"(N) : "memory");
}
__device__ __forceinline__ void ldm_x4(uint32_t addr, uint32_t* r) {
    asm volatile("ldmatrix.sync.aligned.m8n8.x4.shared.b16 {%0,%1,%2,%3}, [%4];"
        : "=r"(r[0]), "=r"(r[1]), "=r"(r[2]), "=r"(r[3]) : "r"(addr));
}
// fp16 m16n8k16 MMA, fp32 accumulate
__device__ __forceinline__ void mma_f16(float* d, const uint32_t* a, const uint32_t* b) {
    asm volatile("mma.sync.aligned.m16n8k16.row.col.f32.f16.f16.f32 "
        "{%0,%1,%2,%3}, {%4,%5,%6,%7}, {%8,%9}, {%0,%1,%2,%3};"
        : "+f"(d[0]), "+f"(d[1]), "+f"(d[2]), "+f"(d[3])
        : "r"(a[0]), "r"(a[1]), "r"(a[2]), "r"(a[3]), "r"(b[0]), "r"(b[1]));
}
// single-MUFU tanh (error ~1e-4, below our fp16 output rounding)
__device__ __forceinline__ float tanh_fast(float x) {
    float y;
    asm("tanh.approx.f32 %0, %1;" : "=f"(y) : "f"(x));
    return y;
}
// swizzled offset inside a tile: row r (64B rows), 16B-chunk c (0..3)
__device__ __forceinline__ uint32_t sw_off(int r, int c) {
    return ((uint32_t)r << 6) + (uint32_t)((c ^ ((r >> 1) & 3)) << 4);
}

// ---------------- small kernels: spectral norm ----------------
__global__ void init_vec_kernel(float* v, int n, float val) {
    int i = blockIdx.x * blockDim.x + threadIdx.x;
    if (i < n) v[i] = val;
}

// y[row] = dot(W[row,:], v); float4 loads; optionally zeros zout[0..nz).
__global__ void matvec_rows(const float* __restrict__ W, const float* __restrict__ v,
                            float* __restrict__ y, int C,
                            float* __restrict__ zout, int nz) {
    if (zout) {
        int gi = blockIdx.x * blockDim.x + threadIdx.x;
        if (gi < nz) zout[gi] = 0.f;
    }
    int row = blockIdx.x;
    const float4* Wr = reinterpret_cast<const float4*>(W + (size_t)row * C);
    const float4* v4 = reinterpret_cast<const float4*>(v);
    int C4 = C >> 2;
    float acc = 0.f;
    for (int j = threadIdx.x; j < C4; j += 256) {
        float4 a = Wr[j];
        float4 b = v4[j];
        acc += a.x * b.x + a.y * b.y + a.z * b.z + a.w * b.w;
    }
    __shared__ float sm[8];
    #pragma unroll
    for (int o = 16; o > 0; o >>= 1) acc += __shfl_down_sync(0xffffffffu, acc, o);
    if ((threadIdx.x & 31) == 0) sm[threadIdx.x >> 5] = acc;
    __syncthreads();
    if (threadIdx.x < 8) {
        float a = sm[threadIdx.x];
        #pragma unroll
        for (int o = 4; o > 0; o >>= 1) a += __shfl_down_sync(0xffu, a, o);
        if (threadIdx.x == 0) y[row] = a;
    }
}

// z[col] += partial dot(W[:,col], u); grid (C/32, 8); z must be zeroed first
__global__ void matvec_cols(const float* __restrict__ W, const float* __restrict__ u,
                            float* __restrict__ z, int R, int C) {
    int lane = threadIdx.x & 31;
    int rp   = threadIdx.x >> 5;
    int col  = blockIdx.x * 32 + lane;
    int rchunk = R >> 3;
    int r0 = blockIdx.y * rchunk;
    int r1 = r0 + rchunk;
    float acc = 0.f;
    for (int i = r0 + rp; i < r1; i += 8) acc += W[(size_t)i * C + col] * u[i];
    __shared__ float sm[8][33];
    sm[rp][lane] = acc;
    __syncthreads();
    if (rp == 0) {
        float a = 0.f;
        #pragma unroll
        for (int r = 0; r < 8; r++) a += sm[r][lane];
        atomicAdd(&z[col], a);
    }
}

// sigma = (u . t) / (||u|| * ||v||); single 1024-thread block.
__global__ void finalize_sigma(const float* __restrict__ u, const float* __restrict__ t,
                               const float* __restrict__ v, int R, int C,
                               float* __restrict__ sig) {
    float du = 0.f, nu = 0.f, nv = 0.f;
    for (int i = threadIdx.x; i < R; i += 1024) {
        float ui = u[i];
        du += ui * t[i];
        nu += ui * ui;
    }
    for (int i = threadIdx.x; i < C; i += 1024) {
        float vi = v[i];
        nv += vi * vi;
    }
    __shared__ float s1[32], s2[32], s3[32];
    #pragma unroll
    for (int o = 16; o > 0; o >>= 1) {
        du += __shfl_down_sync(0xffffffffu, du, o);
        nu += __shfl_down_sync(0xffffffffu, nu, o);
        nv += __shfl_down_sync(0xffffffffu, nv, o);
    }
    if ((threadIdx.x & 31) == 0) {
        s1[threadIdx.x >> 5] = du; s2[threadIdx.x >> 5] = nu; s3[threadIdx.x >> 5] = nv;
    }
    __syncthreads();
    if (threadIdx.x < 32) {
        float a = s1[threadIdx.x], b = s2[threadIdx.x], c = s3[threadIdx.x];
        #pragma unroll
        for (int o = 16; o > 0; o >>= 1) {
            a += __shfl_down_sync(0xffffffffu, a, o);
            b += __shfl_down_sync(0xffffffffu, b, o);
            c += __shfl_down_sync(0xffffffffu, c, o);
        }
        if (threadIdx.x == 0)
            sig[0] = a / (sqrtf(b) * sqrtf(c) + 1e-12f);
    }
}

// Wh = fp16(W / sigma), float4 loads
__global__ void scale_half(const float* __restrict__ W, const float* __restrict__ sig,
                           __half* __restrict__ Wh, size_t n) {
    float inv = 1.0f / sig[0];
    size_t n4 = n >> 2;
    size_t stride = (size_t)gridDim.x * blockDim.x;
    const float4* W4 = reinterpret_cast<const float4*>(W);
    for (size_t i = (size_t)blockIdx.x * blockDim.x + threadIdx.x; i < n4; i += stride) {
        float4 w = W4[i];
        __half2 a, b;
        a.x = __float2half_rn(w.x * inv); a.y = __float2half_rn(w.y * inv);
        b.x = __float2half_rn(w.z * inv); b.y = __float2half_rn(w.w * inv);
        *reinterpret_cast<__half2*>(Wh + i * 4)     = a;
        *reinterpret_cast<__half2*>(Wh + i * 4 + 2) = b;
    }
}

// ---------------- layernorm: fp32 in, fp16 out ----------------
__global__ void layernorm_half(const float* __restrict__ h,
                               const float* __restrict__ g, const float* __restrict__ b,
                               __half* __restrict__ o) {
    int row = blockIdx.x;
    const float* hr = h + (size_t)row * DH;
    float s = 0.f, ss = 0.f;
    float xl[4];
    #pragma unroll
    for (int t = 0; t < 4; t++) {
        float x = hr[threadIdx.x + t * 256];
        xl[t] = x; s += x; ss += x * x;
    }
    __shared__ float sm1[8], sm2[8];
    #pragma unroll
    for (int o2 = 16; o2 > 0; o2 >>= 1) {
        s  += __shfl_down_sync(0xffffffffu, s, o2);
        ss += __shfl_down_sync(0xffffffffu, ss, o2);
    }
    if ((threadIdx.x & 31) == 0) { sm1[threadIdx.x >> 5] = s; sm2[threadIdx.x >> 5] = ss; }
    __syncthreads();
    __shared__ float s_mu, s_inv;
    if (threadIdx.x < 8) {
        float a = sm1[threadIdx.x], c = sm2[threadIdx.x];
        #pragma unroll
        for (int o2 = 4; o2 > 0; o2 >>= 1) {
            a += __shfl_down_sync(0xffu, a, o2);
            c += __shfl_down_sync(0xffu, c, o2);
        }
        if (threadIdx.x == 0) {
            float mu  = a * (1.0f / DH);
            float var = c * (1.0f / DH) - mu * mu;
            s_mu = mu; s_inv = rsqrtf(var + LN_EPSF);
        }
    }
    __syncthreads();
    float mu = s_mu, inv = s_inv;
    #pragma unroll
    for (int t = 0; t < 4; t++) {
        int j = threadIdx.x + t * 256;
        float y = (xl[t] - mu) * inv * g[j] + b[j];
        o[(size_t)row * DH + j] = __float2half_rn(y);
    }
}

// ---------------- fp16 single-term persistent GEMM ----------------
// C[M,N] = A[M,K] @ (Wh[N,K])^T, both fp16, fp32 accumulate.
// CTA tile 256x128, 8 warps (4x2), warp tile 64x64 = 4x8 m16n8k16 frags.
// BK=32, 4-stage cp.async, 64B XOR-swizzled rows, persistent CTAs.
#define MSTAGES 4
#define ATILEB  (256 * 64)               // 16384 B: 256x32 fp16 tile
#define WTILEB  (128 * 64)               //  8192 B: 128x32 fp16 tile
#define STAGEB  (ATILEB + WTILEB)        // 24576 B
#define GSMEM   (MSTAGES * STAGEB)       // 98304 B

#define EPI_TANH 1
#define EPI_STEP 2

__device__ __forceinline__ void load_stage(
    uint32_t sbase, int buf, int k0,
    const __half* __restrict__ A, const __half* __restrict__ Wh,
    int bm, int bn, int K, int tid)
{
    uint32_t base = sbase + (uint32_t)buf * STAGEB;
    // A: 256 rows x 4 16B-chunks = 1024 lane-ops (4/thread)
    #pragma unroll
    for (int j = 0; j < 4; j++) {
        int c = tid + j * 256;                  // 0..1023
        int rr = c >> 2, c16 = c & 3;
        cp_async16(base + sw_off(rr, c16),
                   A + (size_t)(bm + rr) * K + k0 + c16 * 8);
    }
    // W: 128 rows x 4 chunks = 512 lane-ops (2/thread)
    #pragma unroll
    for (int j = 0; j < 2; j++) {
        int c = tid + j * 256;                  // 0..511
        int rr = c >> 2, c16 = c & 3;
        cp_async16(base + (uint32_t)ATILEB + sw_off(rr, c16),
                   Wh + (size_t)(bn + rr) * K + k0 + c16 * 8);
    }
}

template <int EPI>
__global__ __launch_bounds__(256, 1) void gemm_f16(
    const __half* __restrict__ A, const __half* __restrict__ Wh,
    const float* __restrict__ bias, int N, int K, int ntiles, int nx,
    float* __restrict__ Cf, __half* __restrict__ Ch,
    const float* __restrict__ hprev, const float* __restrict__ xemb, float gamma) {

    extern __shared__ __align__(128) char smem[];
    uint32_t sb = smem_u32(smem);
    int tid = threadIdx.x, wid = tid >> 5, lane = tid & 31;
    int m0 = (wid >> 1) * 64, n0 = (wid & 1) * 64;   // warp tile 64x64
    int r16 = lane & 15, kh = lane >> 4;
    int g8 = lane >> 3, l8 = lane & 7;
    int qr = lane >> 2, qc = (lane & 3) * 2;
    const int nch = K >> 5;

    for (int tile = blockIdx.x; tile < ntiles; tile += gridDim.x) {
        int bm = (tile / nx) * 256, bn = (tile % nx) * 128;

        float acc[4][8][4] = {};

        #pragma unroll
        for (int s = 0; s < MSTAGES - 1; s++) {
            load_stage(sb, s, s << 5, A, Wh, bm, bn, K, tid);
            cp_commit();
        }

        for (int i = 0; i < nch; i++) {
            cp_wait<MSTAGES - 2>();
            __syncthreads();

            uint32_t st = sb + (uint32_t)(i & (MSTAGES - 1)) * STAGEB;
            #pragma unroll
            for (int ks = 0; ks < 2; ks++) {
                uint32_t a[4][4], w[4][4];
                #pragma unroll
                for (int mt = 0; mt < 4; mt++)
                    ldm_x4(st + sw_off(m0 + mt * 16 + r16, ks * 2 + kh), a[mt]);
                #pragma unroll
                for (int nh = 0; nh < 4; nh++)
                    ldm_x4(st + ATILEB +
                           sw_off(n0 + nh * 16 + (g8 >> 1) * 8 + l8, ks * 2 + (g8 & 1)),
                           w[nh]);
                #pragma unroll
                for (int mt = 0; mt < 4; mt++)
                    #pragma unroll
                    for (int nt = 0; nt < 8; nt++)
                        mma_f16(acc[mt][nt], a[mt], &w[nt >> 1][(nt & 1) * 2]);
            }

            int nxt = i + MSTAGES - 1;
            if (nxt < nch)
                load_stage(sb, nxt & (MSTAGES - 1), nxt << 5, A, Wh, bm, bn, K, tid);
            cp_commit();
        }

        // epilogue from accumulator registers
        #pragma unroll
        for (int mt = 0; mt < 4; mt++) {
            #pragma unroll
            for (int nt = 0; nt < 8; nt++) {
                int c0 = bn + n0 + nt * 8 + qc;
                float2 bz = *(const float2*)(bias + c0);
                #pragma unroll
                for (int h = 0; h < 2; h++) {
                    int r = bm + m0 + mt * 16 + qr + h * 8;
                    float v0 = acc[mt][nt][h * 2 + 0] + bz.x;
                    float v1 = acc[mt][nt][h * 2 + 1] + bz.y;
                    size_t idx = (size_t)r * N + c0;
                    if (EPI == EPI_TANH) {
                        __half2 hp;
                        hp.x = __float2half_rn(tanh_fast(v0));
                        hp.y = __float2half_rn(tanh_fast(v1));
                        *(__half2*)(Ch + idx) = hp;
                    } else {
                        float2 hp = *(const float2*)(hprev + idx);
                        float2 xe = *(const float2*)(xemb + idx);
                        float2 o;
                        o.x = (1.0f - gamma) * hp.x + gamma * (v0 + xe.x);
                        o.y = (1.0f - gamma) * hp.y + gamma * (v1 + xe.y);
                        *(float2*)(Cf + idx) = o;
                    }
                }
            }
        }
        __syncthreads();   // protect smem buffers before next tile's prologue
    }
}

// ---------------- fp32 SIMT GEMM (embed + head only) ----------------
#define BM 128
#define BN 128
#define BK 8
#define TM 8
#define TN 8

__global__ __launch_bounds__(256, 2) void gemm_f32_bias(
    const float* __restrict__ A, const float* __restrict__ W,
    const float* __restrict__ bias, float* __restrict__ C,
    int M, int N, int K) {

    __shared__ __align__(16) float As[BK][BM];
    __shared__ __align__(16) float Ws[BK][BN];

    int tid = threadIdx.x;
    int bm = blockIdx.y * BM, bn = blockIdx.x * BN;
    const float* Ablk = A + (size_t)bm * K;
    const float* Wblk = W + (size_t)bn * K;

    int lrow = tid >> 1;
    int lcol = (tid & 1) * 4;
    int ty = tid >> 4, tx = tid & 15;

    float acc[TM][TN] = {};

    for (int k0 = 0; k0 < K; k0 += BK) {
        float4 a4 = *reinterpret_cast<const float4*>(Ablk + (size_t)lrow * K + k0 + lcol);
        float4 w4 = *reinterpret_cast<const float4*>(Wblk + (size_t)lrow * K + k0 + lcol);
        As[lcol + 0][lrow] = a4.x; As[lcol + 1][lrow] = a4.y;
        As[lcol + 2][lrow] = a4.z; As[lcol + 3][lrow] = a4.w;
        Ws[lcol + 0][lrow] = w4.x; Ws[lcol + 1][lrow] = w4.y;
        Ws[lcol + 2][lrow] = w4.z; Ws[lcol + 3][lrow] = w4.w;
        __syncthreads();
        #pragma unroll
        for (int k = 0; k < BK; k++) {
            float4 a0 = *reinterpret_cast<const float4*>(&As[k][ty * TM]);
            float4 a1 = *reinterpret_cast<const float4*>(&As[k][ty * TM + 4]);
            float4 w0 = *reinterpret_cast<const float4*>(&Ws[k][tx * TN]);
            float4 w1 = *reinterpret_cast<const float4*>(&Ws[k][tx * TN + 4]);
            float ra[TM] = {a0.x, a0.y, a0.z, a0.w, a1.x, a1.y, a1.z, a1.w};
            float rw[TN] = {w0.x, w0.y, w0.z, w0.w, w1.x, w1.y, w1.z, w1.w};
            #pragma unroll
            for (int i = 0; i < TM; i++)
                #pragma unroll
                for (int j = 0; j < TN; j++)
                    acc[i][j] += ra[i] * rw[j];
        }
        __syncthreads();
    }

    #pragma unroll
    for (int i = 0; i < TM; i++) {
        int m = bm + ty * TM + i;
        #pragma unroll
        for (int j = 0; j < TN; j++) {
            int n = bn + tx * TN + j;
            C[(size_t)m * N + n] = acc[i][j] + bias[n];
        }
    }
}

// ---------------- host-side helpers ----------------
// Unnormalized power iteration (scale-invariant); sigma assembled at the end.
static void spectral_sigma(const float* W, int R, int C,
                           float* u, float* va, float* vb, float* t, float* sig) {
    float v0 = 1.0f / sqrtf((float)C);
    init_vec_kernel<<<(C + 255) / 256, 256>>>(va, C, v0);
    float* cur = va;
    float* oth = vb;
    for (int it = 0; it < 15; it++) {
        // u = W * cur (and zero oth for the accumulation below)
        matvec_rows<<<R, 256>>>(W, cur, u, C, oth, C);
        // oth += W^T * u
        matvec_cols<<<dim3(C / 32, 8), 256>>>(W, u, oth, R, C);
        float* tmp = cur; cur = oth; oth = tmp;
    }
    // t = W * v_raw ; sigma = (u.t) / (||u|| ||v||)
    matvec_rows<<<R, 256>>>(W, cur, t, C, nullptr, 0);
    finalize_sigma<<<1, 1024>>>(u, t, cur, R, C, sig);
}

extern "C" void kernel_launch(void* const* d_in, const int* in_sizes, int n_in,
                              void* d_out, int out_size) {
    const float* x       = (const float*)d_in[0];
    const float* embed_w = (const float*)d_in[1];
    const float* embed_b = (const float*)d_in[2];
    const float* W1      = (const float*)d_in[3];
    const float* b1      = (const float*)d_in[4];
    const float* W2      = (const float*)d_in[5];
    const float* b2      = (const float*)d_in[6];
    const float* ln_g    = (const float*)d_in[7];
    const float* ln_b    = (const float*)d_in[8];
    const float* head_w  = (const float*)d_in[9];
    const float* head_b  = (const float*)d_in[10];
    float* out = (float*)d_out;

    float *p_xemb, *p_hA, *p_hB, *p_u, *p_v0, *p_v1, *p_t, *p_sig;
    __half *p_W1h, *p_W2h, *p_hn, *p_hid;
    cudaGetSymbolAddress((void**)&p_xemb, g_xemb);
    cudaGetSymbolAddress((void**)&p_hA, g_hA);
    cudaGetSymbolAddress((void**)&p_hB, g_hB);
    cudaGetSymbolAddress((void**)&p_u, g_u);
    cudaGetSymbolAddress((void**)&p_v0, g_v0);
    cudaGetSymbolAddress((void**)&p_v1, g_v1);
    cudaGetSymbolAddress((void**)&p_t, g_t);
    cudaGetSymbolAddress((void**)&p_sig, g_sig);
    cudaGetSymbolAddress((void**)&p_W1h, g_W1h);
    cudaGetSymbolAddress((void**)&p_W2h, g_W2h);
    cudaGetSymbolAddress((void**)&p_hn, g_hn);
    cudaGetSymbolAddress((void**)&p_hid, g_hid);

    cudaFuncSetAttribute(gemm_f16<EPI_TANH>,
                         cudaFuncAttributeMaxDynamicSharedMemorySize, GSMEM);
    cudaFuncSetAttribute(gemm_f16<EPI_STEP>,
                         cudaFuncAttributeMaxDynamicSharedMemorySize, GSMEM);

    // spectral sigma + fp16 weights
    spectral_sigma(W1, DFF, DH, p_u, p_v0, p_v1, p_t, p_sig);
    scale_half<<<2048, 256>>>(W1, p_sig, p_W1h, (size_t)DFF * DH);
    spectral_sigma(W2, DH, DFF, p_u, p_v0, p_v1, p_t, p_sig + 1);
    scale_half<<<2048, 256>>>(W2, p_sig + 1, p_W2h, (size_t)DH * DFF);

    // x_emb = x @ embed_w^T + embed_b  (fp32 SIMT)
    gemm_f32_bias<<<dim3(DH / BN, B_ / BM), 256>>>(x, embed_w, embed_b, p_xemb, B_, DH, DIN);

    // h0 = x_emb
    cudaMemcpyAsync(p_hA, p_xemb, (size_t)B_ * DH * sizeof(float), cudaMemcpyDeviceToDevice);

    const int nt1 = (B_ / 256) * (DFF / 128);   // 512 tiles, nx=32
    const int nt2 = (B_ / 256) * (DH / 128);    // 128 tiles, nx=8

    float* hc = p_hA;
    float* hx = p_hB;
    for (int s = 0; s < STEPS; s++) {
        layernorm_half<<<B_, 256>>>(hc, ln_g, ln_b, p_hn);
        gemm_f16<EPI_TANH><<<NSM, 256, GSMEM>>>(
            p_hn, p_W1h, b1, DFF, DH, nt1, DFF / 128,
            nullptr, p_hid, nullptr, nullptr, 0.f);
        gemm_f16<EPI_STEP><<<NSM, 256, GSMEM>>>(
            p_hid, p_W2h, b2, DH, DFF, nt2, DH / 128,
            hx, nullptr, hc, p_xemb, GAMMA_F);
        float* tmp = hc; hc = hx; hx = tmp;
    }

    // out = h @ head_w^T + head_b (fp32 SIMT)
    gemm_f32_bias<<<dim3(DOUT / BN, B_ / BM), 256>>>(hc, head_w, head_b, out, B_, DOUT, DH);
}

// round 13
// speedup vs baseline: 6.7501x; 1.0103x over previous
#include <cuda_runtime.h>
#include <cuda_fp16.h>
#include <math.h>
#include <cstddef>
#include <cstdint>

// ---------------- problem constants ----------------
#define B_    4096
#define DIN   512
#define DH    1024
#define DOUT  256
#define DFF   4096
#define STEPS 30
#define LN_EPSF 1e-5f
#define GAMMA_F 0.17677669529663687f   // 0.5*sqrt(64/512)
#define NSM   148

// ---------------- device scratch (no allocations allowed) ----------------
__device__ float g_xemb[(size_t)B_ * DH];   // also scratch: V^T (16MB) during spectral
__device__ float g_hA[(size_t)B_ * DH];     // also scratch: Gram B (4MB) during spectral
__device__ float g_hB[(size_t)B_ * DH];
__device__ __half g_W1h[(size_t)DFF * DH];
__device__ __half g_W2h[(size_t)DH * DFF];
__device__ __half g_hn[(size_t)B_ * DH];
__device__ __half g_hid[(size_t)B_ * DFF];  // also scratch: Vhi/Vlo (8MB each) during spectral
__device__ float g_u[4096];
__device__ float g_v0[4096];
__device__ float g_v1[4096];
__device__ float g_t[4096];
__device__ float g_sig[2];

// ---------------- low-level helpers (plain sm_80+ features only) ----------------
__device__ __forceinline__ uint32_t smem_u32(const void* p) {
    uint32_t a;
    asm("{ .reg .u64 t; cvta.to.shared.u64 t, %1; cvt.u32.u64 %0, t; }" : "=r"(a) : "l"(p));
    return a;
}
__device__ __forceinline__ void cp_async16(uint32_t dst, const void* src) {
    asm volatile("cp.async.cg.shared.global [%0], [%1], 16;" :: "r"(dst), "l"(src) : "memory");
}
__device__ __forceinline__ void cp_commit() {
    asm volatile("cp.async.commit_group;" ::: "memory");
}
template<int N> __device__ __forceinline__ void cp_wait() {
    asm volatile("cp.async.wait_group %0;" :: "n"(N) : "memory");
}
__device__ __forceinline__ void ldm_x4(uint32_t addr, uint32_t* r) {
    asm volatile("ldmatrix.sync.aligned.m8n8.x4.shared.b16 {%0,%1,%2,%3}, [%4];"
        : "=r"(r[0]), "=r"(r[1]), "=r"(r[2]), "=r"(r[3]) : "r"(addr));
}
__device__ __forceinline__ void mma_f16(float* d, const uint32_t* a, const uint32_t* b) {
    asm volatile("mma.sync.aligned.m16n8k16.row.col.f32.f16.f16.f32 "
        "{%0,%1,%2,%3}, {%4,%5,%6,%7}, {%8,%9}, {%0,%1,%2,%3};"
        : "+f"(d[0]), "+f"(d[1]), "+f"(d[2]), "+f"(d[3])
        : "r"(a[0]), "r"(a[1]), "r"(a[2]), "r"(a[3]), "r"(b[0]), "r"(b[1]));
}
__device__ __forceinline__ float tanh_fast(float x) {
    float y;
    asm("tanh.approx.f32 %0, %1;" : "=f"(y) : "f"(x));
    return y;
}
// swizzled offset inside a tile: row r (64B rows), 16B-chunk c (0..3)
__device__ __forceinline__ uint32_t sw_off(int r, int c) {
    return ((uint32_t)r << 6) + (uint32_t)((c ^ ((r >> 1) & 3)) << 4);
}

// ---------------- small kernels ----------------
__global__ void init_vec_kernel(float* v, size_t n, float val) {
    size_t i = (size_t)blockIdx.x * blockDim.x + threadIdx.x;
    if (i < n) v[i] = val;
}

// out[C][R] = in[R][C]^T, 32x32 tiles, 256 threads
__global__ void transpose_kernel(const float* __restrict__ in, float* __restrict__ out,
                                 int R, int C) {
    __shared__ float tile[32][33];
    int tx = threadIdx.x & 31, ty = threadIdx.x >> 5;   // 32 x 8
    int bx = blockIdx.x * 32;   // col in 'in'
    int by = blockIdx.y * 32;   // row in 'in'
    #pragma unroll
    for (int p = 0; p < 4; p++)
        tile[ty + p * 8][tx] = in[(size_t)(by + ty + p * 8) * C + bx + tx];
    __syncthreads();
    #pragma unroll
    for (int p = 0; p < 4; p++)
        out[(size_t)(bx + ty + p * 8) * R + by + tx] = tile[tx][ty + p * 8];
}

// fp32 -> fp16 hi/lo split (float4 loads)
__global__ void split_hilo(const float* __restrict__ in,
                           __half* __restrict__ hi, __half* __restrict__ lo, size_t n) {
    size_t n4 = n >> 2;
    size_t stride = (size_t)gridDim.x * blockDim.x;
    const float4* in4 = reinterpret_cast<const float4*>(in);
    for (size_t i = (size_t)blockIdx.x * blockDim.x + threadIdx.x; i < n4; i += stride) {
        float4 w = in4[i];
        __half h0 = __float2half_rn(w.x), h1 = __float2half_rn(w.y);
        __half h2 = __float2half_rn(w.z), h3 = __float2half_rn(w.w);
        __half2 a, b, c, d;
        a.x = h0; a.y = h1; b.x = h2; b.y = h3;
        c.x = __float2half_rn(w.x - __half2float(h0));
        c.y = __float2half_rn(w.y - __half2float(h1));
        d.x = __float2half_rn(w.z - __half2float(h2));
        d.y = __float2half_rn(w.w - __half2float(h3));
        *reinterpret_cast<__half2*>(hi + i * 4)     = a;
        *reinterpret_cast<__half2*>(hi + i * 4 + 2) = b;
        *reinterpret_cast<__half2*>(lo + i * 4)     = c;
        *reinterpret_cast<__half2*>(lo + i * 4 + 2) = d;
    }
}

// y[row] = dot(W[row,:], v); float4 loads (used once for u_raw = W2 @ v0)
__global__ void matvec_rows(const float* __restrict__ W, const float* __restrict__ v,
                            float* __restrict__ y, int C) {
    int row = blockIdx.x;
    const float4* Wr = reinterpret_cast<const float4*>(W + (size_t)row * C);
    const float4* v4 = reinterpret_cast<const float4*>(v);
    int C4 = C >> 2;
    float acc = 0.f;
    for (int j = threadIdx.x; j < C4; j += 256) {
        float4 a = Wr[j];
        float4 b = v4[j];
        acc += a.x * b.x + a.y * b.y + a.z * b.z + a.w * b.w;
    }
    __shared__ float sm[8];
    #pragma unroll
    for (int o = 16; o > 0; o >>= 1) acc += __shfl_down_sync(0xffffffffu, acc, o);
    if ((threadIdx.x & 31) == 0) sm[threadIdx.x >> 5] = acc;
    __syncthreads();
    if (threadIdx.x < 8) {
        float a = sm[threadIdx.x];
        #pragma unroll
        for (int o = 4; o > 0; o >>= 1) a += __shfl_down_sync(0xffu, a, o);
        if (threadIdx.x == 0) y[row] = a;
    }
}

// y = B @ x, B [n,n] fp32 (L2-resident, n=1024). 8 rows/block, warp per row.
__global__ void bmatvec(const float* __restrict__ B, const float* __restrict__ x,
                        float* __restrict__ y, int n) {
    int row = blockIdx.x * 8 + (threadIdx.x >> 5);
    int lane = threadIdx.x & 31;
    const float4* Br = reinterpret_cast<const float4*>(B + (size_t)row * n);
    const float4* x4 = reinterpret_cast<const float4*>(x);
    int n4 = n >> 2;
    float acc = 0.f;
    for (int j = lane; j < n4; j += 32) {
        float4 a = Br[j], b = x4[j];
        acc += a.x * b.x + a.y * b.y + a.z * b.z + a.w * b.w;
    }
    #pragma unroll
    for (int o = 16; o > 0; o >>= 1) acc += __shfl_down_sync(0xffffffffu, acc, o);
    if (lane == 0) y[row] = acc;
}

// sigma = sqrt( (q.q) / (p.q) )    [v-space formula, W1]
__global__ void sigma_pq(const float* __restrict__ p, const float* __restrict__ q,
                         int n, float* __restrict__ sig) {
    float qq = 0.f, pq = 0.f;
    for (int i = threadIdx.x; i < n; i += 1024) {
        float qi = q[i];
        qq += qi * qi;
        pq += p[i] * qi;
    }
    __shared__ float s1[32], s2[32];
    #pragma unroll
    for (int o = 16; o > 0; o >>= 1) {
        qq += __shfl_down_sync(0xffffffffu, qq, o);
        pq += __shfl_down_sync(0xffffffffu, pq, o);
    }
    if ((threadIdx.x & 31) == 0) { s1[threadIdx.x >> 5] = qq; s2[threadIdx.x >> 5] = pq; }
    __syncthreads();
    if (threadIdx.x < 32) {
        float a = s1[threadIdx.x], b = s2[threadIdx.x];
        #pragma unroll
        for (int o = 16; o > 0; o >>= 1) {
            a += __shfl_down_sync(0xffffffffu, a, o);
            b += __shfl_down_sync(0xffffffffu, b, o);
        }
        if (threadIdx.x == 0) sig[0] = sqrtf(a / b);
    }
}

// sigma = sqrt( (a.b) / (c.b) )    [u-space formula, W2]
__global__ void sigma_cab(const float* __restrict__ c, const float* __restrict__ a,
                          const float* __restrict__ b, int n, float* __restrict__ sig) {
    float ab = 0.f, cb = 0.f;
    for (int i = threadIdx.x; i < n; i += 1024) {
        float bi = b[i];
        ab += a[i] * bi;
        cb += c[i] * bi;
    }
    __shared__ float s1[32], s2[32];
    #pragma unroll
    for (int o = 16; o > 0; o >>= 1) {
        ab += __shfl_down_sync(0xffffffffu, ab, o);
        cb += __shfl_down_sync(0xffffffffu, cb, o);
    }
    if ((threadIdx.x & 31) == 0) { s1[threadIdx.x >> 5] = ab; s2[threadIdx.x >> 5] = cb; }
    __syncthreads();
    if (threadIdx.x < 32) {
        float x = s1[threadIdx.x], y = s2[threadIdx.x];
        #pragma unroll
        for (int o = 16; o > 0; o >>= 1) {
            x += __shfl_down_sync(0xffffffffu, x, o);
            y += __shfl_down_sync(0xffffffffu, y, o);
        }
        if (threadIdx.x == 0) sig[0] = sqrtf(x / y);
    }
}

// Wh = fp16(W / sigma), float4 loads
__global__ void scale_half(const float* __restrict__ W, const float* __restrict__ sig,
                           __half* __restrict__ Wh, size_t n) {
    float inv = 1.0f / sig[0];
    size_t n4 = n >> 2;
    size_t stride = (size_t)gridDim.x * blockDim.x;
    const float4* W4 = reinterpret_cast<const float4*>(W);
    for (size_t i = (size_t)blockIdx.x * blockDim.x + threadIdx.x; i < n4; i += stride) {
        float4 w = W4[i];
        __half2 a, b;
        a.x = __float2half_rn(w.x * inv); a.y = __float2half_rn(w.y * inv);
        b.x = __float2half_rn(w.z * inv); b.y = __float2half_rn(w.w * inv);
        *reinterpret_cast<__half2*>(Wh + i * 4)     = a;
        *reinterpret_cast<__half2*>(Wh + i * 4 + 2) = b;
    }
}

// ---------------- layernorm: fp32 in, fp16 out ----------------
__global__ void layernorm_half(const float* __restrict__ h,
                               const float* __restrict__ g, const float* __restrict__ b,
                               __half* __restrict__ o) {
    int row = blockIdx.x;
    const float* hr = h + (size_t)row * DH;
    float s = 0.f, ss = 0.f;
    float xl[4];
    #pragma unroll
    for (int t = 0; t < 4; t++) {
        float x = hr[threadIdx.x + t * 256];
        xl[t] = x; s += x; ss += x * x;
    }
    __shared__ float sm1[8], sm2[8];
    #pragma unroll
    for (int o2 = 16; o2 > 0; o2 >>= 1) {
        s  += __shfl_down_sync(0xffffffffu, s, o2);
        ss += __shfl_down_sync(0xffffffffu, ss, o2);
    }
    if ((threadIdx.x & 31) == 0) { sm1[threadIdx.x >> 5] = s; sm2[threadIdx.x >> 5] = ss; }
    __syncthreads();
    __shared__ float s_mu, s_inv;
    if (threadIdx.x < 8) {
        float a = sm1[threadIdx.x], c = sm2[threadIdx.x];
        #pragma unroll
        for (int o2 = 4; o2 > 0; o2 >>= 1) {
            a += __shfl_down_sync(0xffu, a, o2);
            c += __shfl_down_sync(0xffu, c, o2);
        }
        if (threadIdx.x == 0) {
            float mu  = a * (1.0f / DH);
            float var = c * (1.0f / DH) - mu * mu;
            s_mu = mu; s_inv = rsqrtf(var + LN_EPSF);
        }
    }
    __syncthreads();
    float mu = s_mu, inv = s_inv;
    #pragma unroll
    for (int t = 0; t < 4; t++) {
        int j = threadIdx.x + t * 256;
        float y = (xl[t] - mu) * inv * g[j] + b[j];
        o[(size_t)row * DH + j] = __float2half_rn(y);
    }
}

// ---------------- Gram kernel: G[1024,1024] = (Vhi+Vlo) @ (Vhi+Vlo)^T (3 terms) ----
// split-K x4 over 128 work units, atomicAdd accumulation into zeroed G.
#define G_MST   4
#define G_ATILE 16384                      // 256x32 fp16
#define G_WTILE 8192                       // 128x32 fp16
#define G_STAGE (2 * G_ATILE + 2 * G_WTILE)   // 49152
#define G_SMEM  (G_MST * G_STAGE)             // 196608

__device__ __forceinline__ void gram_load_stage(
    uint32_t sbase, int buf, int k0,
    const __half* __restrict__ Vhi, const __half* __restrict__ Vlo,
    int bm, int bn, int K, int tid)
{
    uint32_t base = sbase + (uint32_t)buf * G_STAGE;
    #pragma unroll
    for (int j = 0; j < 8; j++) {
        int c = tid + j * 256;                  // 0..2047
        int part = c >> 10;
        int rr = (c & 1023) >> 2, c16 = c & 3;
        const __half* g = part ? Vlo : Vhi;
        cp_async16(base + (uint32_t)part * G_ATILE + sw_off(rr, c16),
                   g + (size_t)(bm + rr) * K + k0 + c16 * 8);
    }
    #pragma unroll
    for (int j = 0; j < 4; j++) {
        int c = tid + j * 256;                  // 0..1023
        int part = c >> 9;
        int rr = (c & 511) >> 2, c16 = c & 3;
        const __half* g = part ? Vlo : Vhi;
        cp_async16(base + 2u * G_ATILE + (uint32_t)part * G_WTILE + sw_off(rr, c16),
                   g + (size_t)(bn + rr) * K + k0 + c16 * 8);
    }
}

__global__ __launch_bounds__(256, 1) void gram_f16x3(
    const __half* __restrict__ Vhi, const __half* __restrict__ Vlo,
    float* __restrict__ G, int N, int K, int nunits, int nx, int kchunks)
{
    extern __shared__ __align__(128) char smem[];
    uint32_t sb = smem_u32(smem);
    int tid = threadIdx.x, wid = tid >> 5, lane = tid & 31;
    int m0 = (wid >> 1) * 64, n0 = (wid & 1) * 64;
    int r16 = lane & 15, kh = lane >> 4;
    int g8 = lane >> 3, l8 = lane & 7;
    int qr = lane >> 2, qc = (lane & 3) * 2;

    for (int unit = blockIdx.x; unit < nunits; unit += gridDim.x) {
        int tile = unit >> 2, kid = unit & 3;
        int bm = (tile / nx) * 256, bn = (tile % nx) * 128;
        int kbase = kid * (kchunks << 5);

        float acc[4][8][4] = {};

        #pragma unroll
        for (int s = 0; s < G_MST - 1; s++) {
            gram_load_stage(sb, s, kbase + (s << 5), Vhi, Vlo, bm, bn, K, tid);
            cp_commit();
        }

        for (int i = 0; i < kchunks; i++) {
            cp_wait<G_MST - 2>();
            __syncthreads();

            uint32_t st = sb + (uint32_t)(i & (G_MST - 1)) * G_STAGE;
            #pragma unroll
            for (int ks = 0; ks < 2; ks++) {
                uint32_t a_hi[4][4], a_lo[4][4], w_hi[4][4], w_lo[4][4];
                #pragma unroll
                for (int mt = 0; mt < 4; mt++) {
                    uint32_t ar = st + sw_off(m0 + mt * 16 + r16, ks * 2 + kh);
                    ldm_x4(ar, a_hi[mt]);
                    ldm_x4(ar + G_ATILE, a_lo[mt]);
                }
                #pragma unroll
                for (int nh = 0; nh < 4; nh++) {
                    uint32_t br = st + 2 * G_ATILE +
                        sw_off(n0 + nh * 16 + (g8 >> 1) * 8 + l8, ks * 2 + (g8 & 1));
                    ldm_x4(br, w_hi[nh]);
                    ldm_x4(br + G_WTILE, w_lo[nh]);
                }
                #pragma unroll
                for (int mt = 0; mt < 4; mt++)
                    #pragma unroll
                    for (int nt = 0; nt < 8; nt++)
                        mma_f16(acc[mt][nt], a_hi[mt], &w_hi[nt >> 1][(nt & 1) * 2]);
                #pragma unroll
                for (int mt = 0; mt < 4; mt++)
                    #pragma unroll
                    for (int nt = 0; nt < 8; nt++)
                        mma_f16(acc[mt][nt], a_hi[mt], &w_lo[nt >> 1][(nt & 1) * 2]);
                #pragma unroll
                for (int mt = 0; mt < 4; mt++)
                    #pragma unroll
                    for (int nt = 0; nt < 8; nt++)
                        mma_f16(acc[mt][nt], a_lo[mt], &w_hi[nt >> 1][(nt & 1) * 2]);
            }

            int nxt = i + G_MST - 1;
            if (nxt < kchunks)
                gram_load_stage(sb, nxt & (G_MST - 1), kbase + (nxt << 5), Vhi, Vlo, bm, bn, K, tid);
            cp_commit();
        }

        #pragma unroll
        for (int mt = 0; mt < 4; mt++) {
            #pragma unroll
            for (int nt = 0; nt < 8; nt++) {
                int c0 = bn + n0 + nt * 8 + qc;
                #pragma unroll
                for (int h = 0; h < 2; h++) {
                    int r = bm + m0 + mt * 16 + qr + h * 8;
                    size_t idx = (size_t)r * N + c0;
                    atomicAdd(&G[idx],     acc[mt][nt][h * 2 + 0]);
                    atomicAdd(&G[idx + 1], acc[mt][nt][h * 2 + 1]);
                }
            }
        }
        __syncthreads();
    }
}

// ---------------- fp16 single-term persistent GEMM ----------------
#define MSTAGES 4
#define ATILEB  (256 * 64)
#define WTILEB  (128 * 64)
#define STAGEB  (ATILEB + WTILEB)
#define GSMEM   (MSTAGES * STAGEB)       // 98304 B

#define EPI_TANH 1
#define EPI_STEP 2

__device__ __forceinline__ void load_stage(
    uint32_t sbase, int buf, int k0,
    const __half* __restrict__ A, const __half* __restrict__ Wh,
    int bm, int bn, int K, int tid)
{
    uint32_t base = sbase + (uint32_t)buf * STAGEB;
    #pragma unroll
    for (int j = 0; j < 4; j++) {
        int c = tid + j * 256;
        int rr = c >> 2, c16 = c & 3;
        cp_async16(base + sw_off(rr, c16),
                   A + (size_t)(bm + rr) * K + k0 + c16 * 8);
    }
    #pragma unroll
    for (int j = 0; j < 2; j++) {
        int c = tid + j * 256;
        int rr = c >> 2, c16 = c & 3;
        cp_async16(base + (uint32_t)ATILEB + sw_off(rr, c16),
                   Wh + (size_t)(bn + rr) * K + k0 + c16 * 8);
    }
}

template <int EPI>
__global__ __launch_bounds__(256, 1) void gemm_f16(
    const __half* __restrict__ A, const __half* __restrict__ Wh,
    const float* __restrict__ bias, int N, int K, int ntiles, int nx,
    float* __restrict__ Cf, __half* __restrict__ Ch,
    const float* __restrict__ hprev, const float* __restrict__ xemb, float gamma) {

    extern __shared__ __align__(128) char smem[];
    uint32_t sb = smem_u32(smem);
    int tid = threadIdx.x, wid = tid >> 5, lane = tid & 31;
    int m0 = (wid >> 1) * 64, n0 = (wid & 1) * 64;
    int r16 = lane & 15, kh = lane >> 4;
    int g8 = lane >> 3, l8 = lane & 7;
    int qr = lane >> 2, qc = (lane & 3) * 2;
    const int nch = K >> 5;

    for (int tile = blockIdx.x; tile < ntiles; tile += gridDim.x) {
        int bm = (tile / nx) * 256, bn = (tile % nx) * 128;

        float acc[4][8][4] = {};

        #pragma unroll
        for (int s = 0; s < MSTAGES - 1; s++) {
            load_stage(sb, s, s << 5, A, Wh, bm, bn, K, tid);
            cp_commit();
        }

        for (int i = 0; i < nch; i++) {
            cp_wait<MSTAGES - 2>();
            __syncthreads();

            uint32_t st = sb + (uint32_t)(i & (MSTAGES - 1)) * STAGEB;
            #pragma unroll
            for (int ks = 0; ks < 2; ks++) {
                uint32_t a[4][4], w[4][4];
                #pragma unroll
                for (int mt = 0; mt < 4; mt++)
                    ldm_x4(st + sw_off(m0 + mt * 16 + r16, ks * 2 + kh), a[mt]);
                #pragma unroll
                for (int nh = 0; nh < 4; nh++)
                    ldm_x4(st + ATILEB +
                           sw_off(n0 + nh * 16 + (g8 >> 1) * 8 + l8, ks * 2 + (g8 & 1)),
                           w[nh]);
                #pragma unroll
                for (int mt = 0; mt < 4; mt++)
                    #pragma unroll
                    for (int nt = 0; nt < 8; nt++)
                        mma_f16(acc[mt][nt], a[mt], &w[nt >> 1][(nt & 1) * 2]);
            }

            int nxt = i + MSTAGES - 1;
            if (nxt < nch)
                load_stage(sb, nxt & (MSTAGES - 1), nxt << 5, A, Wh, bm, bn, K, tid);
            cp_commit();
        }

        #pragma unroll
        for (int mt = 0; mt < 4; mt++) {
            #pragma unroll
            for (int nt = 0; nt < 8; nt++) {
                int c0 = bn + n0 + nt * 8 + qc;
                float2 bz = *(const float2*)(bias + c0);
                #pragma unroll
                for (int h = 0; h < 2; h++) {
                    int r = bm + m0 + mt * 16 + qr + h * 8;
                    float v0 = acc[mt][nt][h * 2 + 0] + bz.x;
                    float v1 = acc[mt][nt][h * 2 + 1] + bz.y;
                    size_t idx = (size_t)r * N + c0;
                    if (EPI == EPI_TANH) {
                        __half2 hp;
                        hp.x = __float2half_rn(tanh_fast(v0));
                        hp.y = __float2half_rn(tanh_fast(v1));
                        *(__half2*)(Ch + idx) = hp;
                    } else {
                        float2 hp = *(const float2*)(hprev + idx);
                        float2 xe = *(const float2*)(xemb + idx);
                        float2 o;
                        o.x = (1.0f - gamma) * hp.x + gamma * (v0 + xe.x);
                        o.y = (1.0f - gamma) * hp.y + gamma * (v1 + xe.y);
                        *(float2*)(Cf + idx) = o;
                    }
                }
            }
        }
        __syncthreads();
    }
}

// ---------------- fp32 SIMT GEMM (embed + head only) ----------------
#define BM 128
#define BN 128
#define BK 8
#define TM 8
#define TN 8

__global__ __launch_bounds__(256, 2) void gemm_f32_bias(
    const float* __restrict__ A, const float* __restrict__ W,
    const float* __restrict__ bias, float* __restrict__ C,
    int M, int N, int K) {

    __shared__ __align__(16) float As[BK][BM];
    __shared__ __align__(16) float Ws[BK][BN];

    int tid = threadIdx.x;
    int bm = blockIdx.y * BM, bn = blockIdx.x * BN;
    const float* Ablk = A + (size_t)bm * K;
    const float* Wblk = W + (size_t)bn * K;

    int lrow = tid >> 1;
    int lcol = (tid & 1) * 4;
    int ty = tid >> 4, tx = tid & 15;

    float acc[TM][TN] = {};

    for (int k0 = 0; k0 < K; k0 += BK) {
        float4 a4 = *reinterpret_cast<const float4*>(Ablk + (size_t)lrow * K + k0 + lcol);
        float4 w4 = *reinterpret_cast<const float4*>(Wblk + (size_t)lrow * K + k0 + lcol);
        As[lcol + 0][lrow] = a4.x; As[lcol + 1][lrow] = a4.y;
        As[lcol + 2][lrow] = a4.z; As[lcol + 3][lrow] = a4.w;
        Ws[lcol + 0][lrow] = w4.x; Ws[lcol + 1][lrow] = w4.y;
        Ws[lcol + 2][lrow] = w4.z; Ws[lcol + 3][lrow] = w4.w;
        __syncthreads();
        #pragma unroll
        for (int k = 0; k < BK; k++) {
            float4 a0 = *reinterpret_cast<const float4*>(&As[k][ty * TM]);
            float4 a1 = *reinterpret_cast<const float4*>(&As[k][ty * TM + 4]);
            float4 w0 = *reinterpret_cast<const float4*>(&Ws[k][tx * TN]);
            float4 w1 = *reinterpret_cast<const float4*>(&Ws[k][tx * TN + 4]);
            float ra[TM] = {a0.x, a0.y, a0.z, a0.w, a1.x, a1.y, a1.z, a1.w};
            float rw[TN] = {w0.x, w0.y, w0.z, w0.w, w1.x, w1.y, w1.z, w1.w};
            #pragma unroll
            for (int i = 0; i < TM; i++)
                #pragma unroll
                for (int j = 0; j < TN; j++)
                    acc[i][j] += ra[i] * rw[j];
        }
        __syncthreads();
    }

    #pragma unroll
    for (int i = 0; i < TM; i++) {
        int m = bm + ty * TM + i;
        #pragma unroll
        for (int j = 0; j < TN; j++) {
            int n = bn + tx * TN + j;
            C[(size_t)m * N + n] = acc[i][j] + bias[n];
        }
    }
}

extern "C" void kernel_launch(void* const* d_in, const int* in_sizes, int n_in,
                              void* d_out, int out_size) {
    const float* x       = (const float*)d_in[0];
    const float* embed_w = (const float*)d_in[1];
    const float* embed_b = (const float*)d_in[2];
    const float* W1      = (const float*)d_in[3];
    const float* b1      = (const float*)d_in[4];
    const float* W2      = (const float*)d_in[5];
    const float* b2      = (const float*)d_in[6];
    const float* ln_g    = (const float*)d_in[7];
    const float* ln_b    = (const float*)d_in[8];
    const float* head_w  = (const float*)d_in[9];
    const float* head_b  = (const float*)d_in[10];
    float* out = (float*)d_out;

    float *p_xemb, *p_hA, *p_hB, *p_u, *p_v0, *p_v1, *p_t, *p_sig;
    __half *p_W1h, *p_W2h, *p_hn, *p_hid;
    cudaGetSymbolAddress((void**)&p_xemb, g_xemb);
    cudaGetSymbolAddress((void**)&p_hA, g_hA);
    cudaGetSymbolAddress((void**)&p_hB, g_hB);
    cudaGetSymbolAddress((void**)&p_u, g_u);
    cudaGetSymbolAddress((void**)&p_v0, g_v0);
    cudaGetSymbolAddress((void**)&p_v1, g_v1);
    cudaGetSymbolAddress((void**)&p_t, g_t);
    cudaGetSymbolAddress((void**)&p_sig, g_sig);
    cudaGetSymbolAddress((void**)&p_W1h, g_W1h);
    cudaGetSymbolAddress((void**)&p_W2h, g_W2h);
    cudaGetSymbolAddress((void**)&p_hn, g_hn);
    cudaGetSymbolAddress((void**)&p_hid, g_hid);

    // scratch aliases (used only before embed / h0 / loop writes)
    float*  p_Vt  = p_xemb;                     // 16MB: W1^T
    float*  p_B   = p_hA;                       // 4MB: Gram matrix
    __half* p_Vhi = p_hid;                      // 8MB
    __half* p_Vlo = p_hid + (size_t)DH * DFF;   // 8MB

    cudaFuncSetAttribute(gemm_f16<EPI_TANH>,
                         cudaFuncAttributeMaxDynamicSharedMemorySize, GSMEM);
    cudaFuncSetAttribute(gemm_f16<EPI_STEP>,
                         cudaFuncAttributeMaxDynamicSharedMemorySize, GSMEM);
    cudaFuncSetAttribute(gram_f16x3,
                         cudaFuncAttributeMaxDynamicSharedMemorySize, G_SMEM);

    // ===== spectral sigma for W1 (v-space: B = W1^T W1) =====
    transpose_kernel<<<dim3(DH / 32, DFF / 32), 256>>>(W1, p_Vt, DFF, DH);
    split_hilo<<<2048, 256>>>(p_Vt, p_Vhi, p_Vlo, (size_t)DH * DFF);
    init_vec_kernel<<<4096, 256>>>(p_B, (size_t)1024 * 1024, 0.f);
    gram_f16x3<<<NSM, 256, G_SMEM>>>(p_Vhi, p_Vlo, p_B, 1024, DFF, 128, 8, 32);
    init_vec_kernel<<<4, 256>>>(p_u, 1024, 0.03125f);   // v0 = 1/sqrt(1024)
    {
        float* cur = p_u;
        float* oth = p_v0;
        for (int it = 0; it < 15; it++) {
            bmatvec<<<128, 256>>>(p_B, cur, oth, 1024);
            float* tmp = cur; cur = oth; oth = tmp;
        }
        // cur = B^15 v0 (q), oth = B^14 v0 (p)
        sigma_pq<<<1, 1024>>>(oth, cur, 1024, p_sig);
    }

    // ===== spectral sigma for W2 (u-space: B' = W2 W2^T) =====
    split_hilo<<<2048, 256>>>(W2, p_Vhi, p_Vlo, (size_t)DH * DFF);
    init_vec_kernel<<<4096, 256>>>(p_B, (size_t)1024 * 1024, 0.f);
    gram_f16x3<<<NSM, 256, G_SMEM>>>(p_Vhi, p_Vlo, p_B, 1024, DFF, 128, 8, 32);
    init_vec_kernel<<<16, 256>>>(p_t, 4096, 0.015625f); // v0 = 1/sqrt(4096)
    matvec_rows<<<DH, 256>>>(W2, p_t, p_u, DFF);        // u_raw = W2 v0 (buf[0])
    {
        float* buf[3] = {p_u, p_v0, p_v1};
        for (int k = 1; k <= 15; k++)
            bmatvec<<<128, 256>>>(p_B, buf[(k - 1) % 3], buf[k % 3], 1024);
        // b = x15 = buf[0], a = x14 = buf[2], c = x13 = buf[1]
        sigma_cab<<<1, 1024>>>(buf[1], buf[2], buf[0], 1024, p_sig + 1);
    }

    // fp16 weights (W / sigma)
    scale_half<<<2048, 256>>>(W1, p_sig, p_W1h, (size_t)DFF * DH);
    scale_half<<<2048, 256>>>(W2, p_sig + 1, p_W2h, (size_t)DH * DFF);

    // x_emb = x @ embed_w^T + embed_b  (fp32 SIMT) -- overwrites Vt scratch
    gemm_f32_bias<<<dim3(DH / BN, B_ / BM), 256>>>(x, embed_w, embed_b, p_xemb, B_, DH, DIN);

    // h0 = x_emb  -- overwrites Gram scratch
    cudaMemcpyAsync(p_hA, p_xemb, (size_t)B_ * DH * sizeof(float), cudaMemcpyDeviceToDevice);

    const int nt1 = (B_ / 256) * (DFF / 128);   // 512 tiles, nx=32
    const int nt2 = (B_ / 256) * (DH / 128);    // 128 tiles, nx=8

    float* hc = p_hA;
    float* hx = p_hB;
    for (int s = 0; s < STEPS; s++) {
        layernorm_half<<<B_, 256>>>(hc, ln_g, ln_b, p_hn);
        gemm_f16<EPI_TANH><<<NSM, 256, GSMEM>>>(
            p_hn, p_W1h, b1, DFF, DH, nt1, DFF / 128,
            nullptr, p_hid, nullptr, nullptr, 0.f);
        gemm_f16<EPI_STEP><<<NSM, 256, GSMEM>>>(
            p_hid, p_W2h, b2, DH, DFF, nt2, DH / 128,
            hx, nullptr, hc, p_xemb, GAMMA_F);
        float* tmp = hc; hc = hx; hx = tmp;
    }

    // out = h @ head_w^T + head_b (fp32 SIMT)
    gemm_f32_bias<<<dim3(DOUT / BN, B_ / BM), 256>>>(hc, head_w, head_b, out, B_, DOUT, DH);
}